// round 4
// baseline (speedup 1.0000x reference)
#include <cuda_runtime.h>

#define N_TOK 4096
#define HEPS 1e-6f
#define NCHUNK 16

// ---------------- scratch (device globals; no allocs allowed) ----------------
__device__ __align__(16) float g_weff_q[256*256];
__device__ __align__(16) float g_weff_k[256*256];
__device__ __align__(16) float g_qf[8*64*N_TOK];   // [h][e][n], heads 4..7 = exp(-h)
__device__ __align__(16) float g_kf[8*64*N_TOK];
__device__ __align__(16) float g_vf[8*64*N_TOK];
__device__ __align__(16) float g_v [256*N_TOK];
__device__ __align__(16) float g_pKV[8*NCHUNK*64*64];
__device__ __align__(16) float g_KV[8*64*64];
__device__ __align__(16) float g_S [8*64];

// ---------------- K0: Weff[o][c] = sum_d Wm[e][d] * Wbig[h*64+d][c] ----------
__global__ void k_weff(const float* __restrict__ Wq, const float* __restrict__ Wk,
                       const float* __restrict__ Wmq, const float* __restrict__ Wmk) {
    int o = blockIdx.x;            // 0..255
    int c = threadIdx.x;           // 0..255
    int h = o >> 6, e = o & 63;
    const float* Wm = blockIdx.y ? Wmk : Wmq;
    const float* Wb = blockIdx.y ? Wk  : Wq;
    float* dst      = blockIdx.y ? g_weff_k : g_weff_q;
    __shared__ float sWm[64];
    if (c < 64) sWm[c] = Wm[e*64 + c];
    __syncthreads();
    float acc = 0.f;
    #pragma unroll 8
    for (int d = 0; d < 64; d++)
        acc += sWm[d] * Wb[(h*64 + d)*256 + c];
    dst[o*256 + c] = acc;
}

// ---------------- K1: hedgehog GEMM: f = exp(+-(Weff @ x2 + bm)) -------------
// 64x64 tile, K=256 in steps of 16, 4x4 microtile per thread (256 threads).
__global__ void k_gemm_hedge(const float* __restrict__ x2,
                             const float* __restrict__ bmq,
                             const float* __restrict__ bmk) {
    __shared__ float As[16][64];
    __shared__ float Bs[16][64];
    const float* Weff = blockIdx.z ? g_weff_k : g_weff_q;
    const float* bm   = blockIdx.z ? bmk : bmq;
    float* f          = blockIdx.z ? g_kf : g_qf;

    int t  = threadIdx.x;
    int m0 = blockIdx.x * 64;
    int n0 = blockIdx.y * 64;
    int tx = t & 15, ty = t >> 4;

    float acc[4][4] = {};
    int lm = t >> 2;              // A-load row within tile
    int lk = (t & 3) * 4;         // A-load k group
    int bk = t >> 4;              // B-load k row
    int bn = (t & 15) * 4;        // B-load n group

    for (int k0 = 0; k0 < 256; k0 += 16) {
        float4 av = *(const float4*)&Weff[(m0 + lm)*256 + k0 + lk];
        As[lk+0][lm] = av.x; As[lk+1][lm] = av.y;
        As[lk+2][lm] = av.z; As[lk+3][lm] = av.w;
        *(float4*)&Bs[bk][bn] = *(const float4*)&x2[(k0 + bk)*N_TOK + n0 + bn];
        __syncthreads();
        #pragma unroll
        for (int kk = 0; kk < 16; kk++) {
            float4 a = *(const float4*)&As[kk][ty*4];
            float4 b = *(const float4*)&Bs[kk][tx*4];
            float ar[4] = {a.x, a.y, a.z, a.w};
            float br[4] = {b.x, b.y, b.z, b.w};
            #pragma unroll
            for (int i = 0; i < 4; i++)
                #pragma unroll
                for (int j = 0; j < 4; j++)
                    acc[i][j] += ar[i] * br[j];
        }
        __syncthreads();
    }

    int n = n0 + tx*4;
    #pragma unroll
    for (int i = 0; i < 4; i++) {
        int r = m0 + ty*4 + i;         // row o = h*64+e, h = r>>6 (<4)
        float bias = bm[r & 63];
        float4 vp, vn;
        float h0 = acc[i][0] + bias, h1 = acc[i][1] + bias;
        float h2 = acc[i][2] + bias, h3 = acc[i][3] + bias;
        vp.x = __expf(h0);  vp.y = __expf(h1);  vp.z = __expf(h2);  vp.w = __expf(h3);
        vn.x = __expf(-h0); vn.y = __expf(-h1); vn.z = __expf(-h2); vn.w = __expf(-h3);
        *(float4*)&f[r*N_TOK + n]                 = vp;
        *(float4*)&f[r*N_TOK + n + 4*64*N_TOK]    = vn;   // concatenated head h+4
    }
}

// ---------------- K2a: depthwise 3x3x3 conv over (H,W,D), pad 1 --------------
__global__ void k_conv(const float* __restrict__ x, const float* __restrict__ Wv,
                       const float* __restrict__ bv) {
    int c  = blockIdx.x;           // 256
    int hh = blockIdx.y;           // 16
    int dd = threadIdx.x;          // 16
    int ww = threadIdx.y;          // 16
    __shared__ float sw[27];
    int t = threadIdx.y*16 + threadIdx.x;
    if (t < 27) sw[t] = Wv[c*27 + t];
    __syncthreads();
    float acc = bv[c];
    #pragma unroll
    for (int a = -1; a <= 1; a++) {
        int hz = hh + a; if (hz < 0 || hz > 15) continue;
        #pragma unroll
        for (int b = -1; b <= 1; b++) {
            int wy = ww + b; if (wy < 0 || wy > 15) continue;
            #pragma unroll
            for (int cc = -1; cc <= 1; cc++) {
                int xd = dd + cc; if (xd < 0 || xd > 15) continue;
                acc += sw[(a+1)*9 + (b+1)*3 + (cc+1)] *
                       x[((c*16 + hz)*16 + wy)*16 + xd];
            }
        }
    }
    g_v[c*N_TOK + (hh*16 + ww)*16 + dd] = acc;
}

// ---------------- K2b: per-head v mix + exp: vf = exp(+-(Wmv@v + bmv)) -------
__global__ void k_vmix(const float* __restrict__ Wmv, const float* __restrict__ bmv) {
    int h  = blockIdx.x;           // 4
    int n0 = blockIdx.y * 64;      // 64 tiles
    __shared__ float sW[64*64];    // 16KB
    __shared__ float sv[64*64];    // 16KB
    int t = threadIdx.x;           // 256
    for (int i = t; i < 4096; i += 256) sW[i] = Wmv[i];
    #pragma unroll
    for (int i = 0; i < 4; i++) {   // 1024 float4 loads / 256 threads
        int j = t + 256*i;
        int d = j >> 4, nn = (j & 15) * 4;
        *(float4*)&sv[d*64 + nn] = *(const float4*)&g_v[(h*64 + d)*N_TOK + n0 + nn];
    }
    __syncthreads();
    #pragma unroll
    for (int i = 0; i < 16; i++) {
        int idx = t + 256*i;
        int e = idx >> 6, nn = idx & 63;
        float acc = bmv[e];
        #pragma unroll 16
        for (int d = 0; d < 64; d++)
            acc += sW[e*64 + d] * sv[d*64 + nn];
        g_vf[(h*64 + e)*N_TOK + n0 + nn]                = __expf(acc);
        g_vf[(h*64 + e)*N_TOK + n0 + nn + 4*64*N_TOK]   = __expf(-acc);
    }
}

// ---------------- K3a: S[h][e] = sum_n kf[h][e][n] (deterministic) -----------
__global__ void k_srow() {
    int row = blockIdx.x;          // 512 = h*64+e
    int t = threadIdx.x;           // 128
    float acc = 0.f;
    for (int n = t; n < N_TOK; n += 128) acc += g_kf[row*N_TOK + n];
    __shared__ float red[128];
    red[t] = acc; __syncthreads();
    for (int s = 64; s > 0; s >>= 1) {
        if (t < s) red[t] += red[t + s];
        __syncthreads();
    }
    if (t == 0) g_S[row] = red[0];
}

// ---------------- K3b: partial KV[h][e][d] over a 256-token chunk ------------
__global__ void k_pkv() {
    int h = blockIdx.x, chunk = blockIdx.y;
    __shared__ float sk[64][33];
    __shared__ float sv[64][33];
    int t = threadIdx.x;           // 256
    int tx = t & 15, ty = t >> 4;
    float acc[4][4] = {};
    int base_n = chunk * 256;
    for (int sub = 0; sub < 8; sub++) {
        int n0 = base_n + sub * 32;
        #pragma unroll
        for (int i = 0; i < 2; i++) {           // 512 float4 / 256 threads
            int j = t + 256*i;
            int e = j >> 3, nf = (j & 7) * 4;
            float4 kq = *(const float4*)&g_kf[(h*64 + e)*N_TOK + n0 + nf];
            sk[e][nf] = kq.x; sk[e][nf+1] = kq.y; sk[e][nf+2] = kq.z; sk[e][nf+3] = kq.w;
            float4 vq = *(const float4*)&g_vf[(h*64 + e)*N_TOK + n0 + nf];
            sv[e][nf] = vq.x; sv[e][nf+1] = vq.y; sv[e][nf+2] = vq.z; sv[e][nf+3] = vq.w;
        }
        __syncthreads();
        #pragma unroll 8
        for (int nn = 0; nn < 32; nn++) {
            float kr[4], vr[4];
            #pragma unroll
            for (int i = 0; i < 4; i++) kr[i] = sk[ty*4 + i][nn];
            #pragma unroll
            for (int j = 0; j < 4; j++) vr[j] = sv[tx*4 + j][nn];
            #pragma unroll
            for (int i = 0; i < 4; i++)
                #pragma unroll
                for (int j = 0; j < 4; j++)
                    acc[i][j] += kr[i] * vr[j];
        }
        __syncthreads();
    }
    float* dst = &g_pKV[(h*NCHUNK + chunk)*64*64];
    #pragma unroll
    for (int i = 0; i < 4; i++)
        #pragma unroll
        for (int j = 0; j < 4; j++)
            dst[(ty*4 + i)*64 + tx*4 + j] = acc[i][j];
}

// ---------------- K3c: reduce partial KV -------------------------------------
__global__ void k_rkv() {
    int h = blockIdx.x;
    int t = threadIdx.x;           // 256
    for (int idx = t; idx < 4096; idx += 256) {
        float acc = 0.f;
        #pragma unroll
        for (int c = 0; c < NCHUNK; c++)
            acc += g_pKV[(h*NCHUNK + c)*4096 + idx];
        g_KV[h*4096 + idx] = acc;
    }
}

// ---------------- K4: out[h*64+d][n] = (qf . KV) / (qf . S + eps) ------------
__global__ void k_out(float* __restrict__ out) {
    int h  = blockIdx.x;           // 8
    int n0 = blockIdx.y * 64;      // 64 tiles
    __shared__ float sKV[64*64];
    __shared__ float sS[64];
    int t = threadIdx.x;           // 256
    for (int i = t; i < 4096; i += 256) sKV[i] = g_KV[h*4096 + i];
    if (t < 64) sS[t] = g_S[h*64 + t];
    __syncthreads();
    int n  = n0 + (t & 63);
    int db = (t >> 6) * 16;
    float4 acc[4] = {};
    float dacc = 0.f;
    for (int e = 0; e < 64; e++) {
        float qv = g_qf[(h*64 + e)*N_TOK + n];
        dacc += qv * sS[e];
        #pragma unroll
        for (int i = 0; i < 4; i++) {
            float4 kvv = *(const float4*)&sKV[e*64 + db + i*4];
            acc[i].x += qv * kvv.x;
            acc[i].y += qv * kvv.y;
            acc[i].z += qv * kvv.z;
            acc[i].w += qv * kvv.w;
        }
    }
    float inv = 1.f / (dacc + HEPS);
    #pragma unroll
    for (int i = 0; i < 4; i++) {
        out[(h*64 + db + i*4 + 0)*N_TOK + n] = acc[i].x * inv;
        out[(h*64 + db + i*4 + 1)*N_TOK + n] = acc[i].y * inv;
        out[(h*64 + db + i*4 + 2)*N_TOK + n] = acc[i].z * inv;
        out[(h*64 + db + i*4 + 3)*N_TOK + n] = acc[i].w * inv;
    }
}

// -----------------------------------------------------------------------------
extern "C" void kernel_launch(void* const* d_in, const int* in_sizes, int n_in,
                              void* d_out, int out_size) {
    const float* x   = (const float*)d_in[0];   // [1,256,16,16,16]
    const float* Wq  = (const float*)d_in[1];   // [256,256]
    const float* Wk  = (const float*)d_in[2];   // [256,256]
    const float* Wv  = (const float*)d_in[3];   // [256,1,3,3,3]
    const float* bv  = (const float*)d_in[4];   // [256]
    const float* Wmq = (const float*)d_in[5];   // [64,64]
    const float* bmq = (const float*)d_in[6];   // [64]
    const float* Wmk = (const float*)d_in[7];   // [64,64]
    const float* bmk = (const float*)d_in[8];   // [64]
    const float* Wmv = (const float*)d_in[9];   // [64,64]
    const float* bmv = (const float*)d_in[10];  // [64]
    float* out = (float*)d_out;                 // [1,512,16,16,16]

    k_weff      <<<dim3(256, 2),        256>>>(Wq, Wk, Wmq, Wmk);
    k_gemm_hedge<<<dim3(4, 64, 2),      256>>>(x, bmq, bmk);
    k_conv      <<<dim3(256, 16), dim3(16,16)>>>(x, Wv, bv);
    k_vmix      <<<dim3(4, 64),         256>>>(Wmv, bmv);
    k_srow      <<<512,                 128>>>();
    k_pkv       <<<dim3(8, NCHUNK),     256>>>();
    k_rkv       <<<8,                   256>>>();
    k_out       <<<dim3(8, 64),         256>>>(out);
}

// round 5
// speedup vs baseline: 1.1390x; 1.1390x over previous
#include <cuda_runtime.h>

#define N_TOK 4096
#define HEPS 1e-6f
#define NCHUNK 32

// ---------------- scratch (device globals; no allocs allowed) ----------------
__device__ __align__(16) float g_weff_q[256*256];
__device__ __align__(16) float g_weff_k[256*256];
__device__ __align__(16) float g_qf[8*64*N_TOK];   // [h][e][n], heads 4..7 = exp(-h)
__device__ __align__(16) float g_kf[8*64*N_TOK];
__device__ __align__(16) float g_vf[8*64*N_TOK];
__device__ __align__(16) float g_v [256*N_TOK];
__device__ __align__(16) float g_pKV[8*NCHUNK*64*64];
__device__ __align__(16) float g_pS [8*NCHUNK*64];
__device__ __align__(16) float g_KV[8*64*64];
__device__ __align__(16) float g_S [8*64];

// ---------------- K0: Weff[o][c] = sum_d Wm[e][d] * Wbig[h*64+d][c] ----------
__global__ void k_weff(const float* __restrict__ Wq, const float* __restrict__ Wk,
                       const float* __restrict__ Wmq, const float* __restrict__ Wmk) {
    int o = blockIdx.x;            // 0..255
    int c = threadIdx.x;           // 0..255
    int h = o >> 6, e = o & 63;
    const float* Wm = blockIdx.y ? Wmk : Wmq;
    const float* Wb = blockIdx.y ? Wk  : Wq;
    float* dst      = blockIdx.y ? g_weff_k : g_weff_q;
    __shared__ float sWm[64];
    if (c < 64) sWm[c] = Wm[e*64 + c];
    __syncthreads();
    float acc = 0.f;
    #pragma unroll 8
    for (int d = 0; d < 64; d++)
        acc += sWm[d] * Wb[(h*64 + d)*256 + c];
    dst[o*256 + c] = acc;
}

// ---------------- K1: hedgehog GEMM: f = exp(+-(Weff @ x2 + bm)) -------------
// 64(M)x128(N) tile, K=256 in steps of 16, 8x8 microtile, 128 threads.
__global__ void k_gemm_hedge(const float* __restrict__ x2,
                             const float* __restrict__ bmq,
                             const float* __restrict__ bmk) {
    __shared__ float As[16][68];    // [k][m], padded
    __shared__ float Bs[16][128];   // [k][n]
    const float* Weff = blockIdx.z ? g_weff_k : g_weff_q;
    const float* bm   = blockIdx.z ? bmk : bmq;
    float* f          = blockIdx.z ? g_kf : g_qf;

    int t  = threadIdx.x;          // 128
    int m0 = blockIdx.x * 64;
    int n0 = blockIdx.y * 128;
    int tx = t & 15, ty = t >> 4;  // 16 x 8

    float acc[8][8] = {};

    for (int k0 = 0; k0 < 256; k0 += 16) {
        #pragma unroll
        for (int i = 0; i < 2; i++) {            // A: 64x16
            int j = t + 128*i;
            int lm = j >> 2, lk = (j & 3) * 4;
            float4 av = *(const float4*)&Weff[(m0 + lm)*256 + k0 + lk];
            As[lk+0][lm] = av.x; As[lk+1][lm] = av.y;
            As[lk+2][lm] = av.z; As[lk+3][lm] = av.w;
        }
        #pragma unroll
        for (int i = 0; i < 4; i++) {            // B: 16x128
            int j = t + 128*i;
            int bk = j >> 5, bn = (j & 31) * 4;
            *(float4*)&Bs[bk][bn] = *(const float4*)&x2[(k0 + bk)*N_TOK + n0 + bn];
        }
        __syncthreads();
        #pragma unroll
        for (int kk = 0; kk < 16; kk++) {
            float a[8], b[8];
            *(float4*)&a[0] = *(const float4*)&As[kk][ty*8];
            *(float4*)&a[4] = *(const float4*)&As[kk][ty*8 + 4];
            *(float4*)&b[0] = *(const float4*)&Bs[kk][tx*8];
            *(float4*)&b[4] = *(const float4*)&Bs[kk][tx*8 + 4];
            #pragma unroll
            for (int i = 0; i < 8; i++)
                #pragma unroll
                for (int j = 0; j < 8; j++)
                    acc[i][j] += a[i] * b[j];
        }
        __syncthreads();
    }

    int n = n0 + tx*8;
    #pragma unroll
    for (int i = 0; i < 8; i++) {
        int r = m0 + ty*8 + i;
        float bias = bm[r & 63];
        float hv[8];
        #pragma unroll
        for (int j = 0; j < 8; j++) hv[j] = acc[i][j] + bias;
        float4 p0, p1, m0v, m1v;
        p0.x = __expf(hv[0]);  p0.y = __expf(hv[1]);  p0.z = __expf(hv[2]);  p0.w = __expf(hv[3]);
        p1.x = __expf(hv[4]);  p1.y = __expf(hv[5]);  p1.z = __expf(hv[6]);  p1.w = __expf(hv[7]);
        m0v.x = __expf(-hv[0]); m0v.y = __expf(-hv[1]); m0v.z = __expf(-hv[2]); m0v.w = __expf(-hv[3]);
        m1v.x = __expf(-hv[4]); m1v.y = __expf(-hv[5]); m1v.z = __expf(-hv[6]); m1v.w = __expf(-hv[7]);
        *(float4*)&f[r*N_TOK + n]                  = p0;
        *(float4*)&f[r*N_TOK + n + 4]              = p1;
        *(float4*)&f[r*N_TOK + n + 4*64*N_TOK]     = m0v;
        *(float4*)&f[r*N_TOK + n + 4 + 4*64*N_TOK] = m1v;
    }
}

// ---------------- K2a: depthwise 3x3x3 conv over (H,W,D), pad 1 --------------
__global__ void k_conv(const float* __restrict__ x, const float* __restrict__ Wv,
                       const float* __restrict__ bv) {
    int c  = blockIdx.x;           // 256
    int hh = blockIdx.y;           // 16
    int dd = threadIdx.x;          // 16
    int ww = threadIdx.y;          // 16
    __shared__ float sw[27];
    int t = threadIdx.y*16 + threadIdx.x;
    if (t < 27) sw[t] = Wv[c*27 + t];
    __syncthreads();
    float acc = bv[c];
    #pragma unroll
    for (int a = -1; a <= 1; a++) {
        int hz = hh + a; if (hz < 0 || hz > 15) continue;
        #pragma unroll
        for (int b = -1; b <= 1; b++) {
            int wy = ww + b; if (wy < 0 || wy > 15) continue;
            #pragma unroll
            for (int cc = -1; cc <= 1; cc++) {
                int xd = dd + cc; if (xd < 0 || xd > 15) continue;
                acc += sw[(a+1)*9 + (b+1)*3 + (cc+1)] *
                       x[((c*16 + hz)*16 + wy)*16 + xd];
            }
        }
    }
    g_v[c*N_TOK + (hh*16 + ww)*16 + dd] = acc;
}

// ---------------- K2b: per-head v mix + exp: vf = exp(+-(Wmv@v + bmv)) -------
// 64x64 tile, K=64 in steps of 16, 8x8 microtile, 64 threads.
__global__ void k_vmix(const float* __restrict__ Wmv, const float* __restrict__ bmv) {
    __shared__ float As[16][68];   // Wmv^T staged: [d][e]
    __shared__ float Bs[16][64];   // v: [d][n]
    int h  = blockIdx.x;           // 4
    int n0 = blockIdx.y * 64;      // 64 tiles
    int t  = threadIdx.x;          // 64
    int tx = t & 7, ty = t >> 3;   // 8 x 8

    float acc[8][8] = {};

    for (int k0 = 0; k0 < 64; k0 += 16) {
        #pragma unroll
        for (int i = 0; i < 4; i++) {            // A: 64(e) x 16(d)
            int j = t + 64*i;
            int lm = j >> 2, lk = (j & 3) * 4;
            float4 av = *(const float4*)&Wmv[lm*64 + k0 + lk];
            As[lk+0][lm] = av.x; As[lk+1][lm] = av.y;
            As[lk+2][lm] = av.z; As[lk+3][lm] = av.w;
        }
        #pragma unroll
        for (int i = 0; i < 4; i++) {            // B: 16(d) x 64(n)
            int j = t + 64*i;
            int bk = j >> 4, bn = (j & 15) * 4;
            *(float4*)&Bs[bk][bn] = *(const float4*)&g_v[(h*64 + k0 + bk)*N_TOK + n0 + bn];
        }
        __syncthreads();
        #pragma unroll
        for (int kk = 0; kk < 16; kk++) {
            float a[8], b[8];
            *(float4*)&a[0] = *(const float4*)&As[kk][ty*8];
            *(float4*)&a[4] = *(const float4*)&As[kk][ty*8 + 4];
            *(float4*)&b[0] = *(const float4*)&Bs[kk][tx*8];
            *(float4*)&b[4] = *(const float4*)&Bs[kk][tx*8 + 4];
            #pragma unroll
            for (int i = 0; i < 8; i++)
                #pragma unroll
                for (int j = 0; j < 8; j++)
                    acc[i][j] += a[i] * b[j];
        }
        __syncthreads();
    }

    int n = n0 + tx*8;
    #pragma unroll
    for (int i = 0; i < 8; i++) {
        int e = ty*8 + i;
        float bias = bmv[e];
        float hv[8];
        #pragma unroll
        for (int j = 0; j < 8; j++) hv[j] = acc[i][j] + bias;
        float4 p0, p1, m0v, m1v;
        p0.x = __expf(hv[0]);  p0.y = __expf(hv[1]);  p0.z = __expf(hv[2]);  p0.w = __expf(hv[3]);
        p1.x = __expf(hv[4]);  p1.y = __expf(hv[5]);  p1.z = __expf(hv[6]);  p1.w = __expf(hv[7]);
        m0v.x = __expf(-hv[0]); m0v.y = __expf(-hv[1]); m0v.z = __expf(-hv[2]); m0v.w = __expf(-hv[3]);
        m1v.x = __expf(-hv[4]); m1v.y = __expf(-hv[5]); m1v.z = __expf(-hv[6]); m1v.w = __expf(-hv[7]);
        float* dst = &g_vf[(h*64 + e)*N_TOK + n];
        *(float4*)&dst[0]               = p0;
        *(float4*)&dst[4]               = p1;
        *(float4*)&dst[4*64*N_TOK]      = m0v;
        *(float4*)&dst[4 + 4*64*N_TOK]  = m1v;
    }
}

// ---------------- K3b: partial KV[h][e][d] + partial S over a 128-token chunk
// 64 threads, 8x8 microtile, 8 substeps of 16 tokens. S fused into the loader.
__global__ void k_pkv() {
    __shared__ float skt[16][68];  // kf transposed: [nn][e]
    __shared__ float svt[16][68];  // vf transposed: [nn][d]
    int h = blockIdx.x, chunk = blockIdx.y;
    int t = threadIdx.x;           // 64
    int tx = t & 7, ty = t >> 3;
    int base_n = chunk * 128;

    float acc[8][8] = {};
    float s[4] = {};               // partial S for rows e = (t>>2) + 16*i

    for (int sub = 0; sub < 8; sub++) {
        int n0 = base_n + sub * 16;
        #pragma unroll
        for (int i = 0; i < 4; i++) {
            int j = t + 64*i;
            int e = j >> 2, nf = (j & 3) * 4;
            float4 kq = *(const float4*)&g_kf[(h*64 + e)*N_TOK + n0 + nf];
            skt[nf+0][e] = kq.x; skt[nf+1][e] = kq.y;
            skt[nf+2][e] = kq.z; skt[nf+3][e] = kq.w;
            s[i] += (kq.x + kq.y) + (kq.z + kq.w);
            float4 vq = *(const float4*)&g_vf[(h*64 + e)*N_TOK + n0 + nf];
            svt[nf+0][e] = vq.x; svt[nf+1][e] = vq.y;
            svt[nf+2][e] = vq.z; svt[nf+3][e] = vq.w;
        }
        __syncthreads();
        #pragma unroll
        for (int nn = 0; nn < 16; nn++) {
            float a[8], b[8];
            *(float4*)&a[0] = *(const float4*)&skt[nn][ty*8];
            *(float4*)&a[4] = *(const float4*)&skt[nn][ty*8 + 4];
            *(float4*)&b[0] = *(const float4*)&svt[nn][tx*8];
            *(float4*)&b[4] = *(const float4*)&svt[nn][tx*8 + 4];
            #pragma unroll
            for (int i = 0; i < 8; i++)
                #pragma unroll
                for (int j = 0; j < 8; j++)
                    acc[i][j] += a[i] * b[j];
        }
        __syncthreads();
    }

    // write partial KV
    float* dst = &g_pKV[(h*NCHUNK + chunk)*64*64];
    #pragma unroll
    for (int i = 0; i < 8; i++) {
        float4 c0 = {acc[i][0], acc[i][1], acc[i][2], acc[i][3]};
        float4 c1 = {acc[i][4], acc[i][5], acc[i][6], acc[i][7]};
        *(float4*)&dst[(ty*8 + i)*64 + tx*8]     = c0;
        *(float4*)&dst[(ty*8 + i)*64 + tx*8 + 4] = c1;
    }

    // reduce & write partial S: 4 loader-lanes per e-row
    #pragma unroll
    for (int i = 0; i < 4; i++) {
        s[i] += __shfl_down_sync(0xffffffffu, s[i], 2);
        s[i] += __shfl_down_sync(0xffffffffu, s[i], 1);
    }
    if ((t & 3) == 0) {
        #pragma unroll
        for (int i = 0; i < 4; i++)
            g_pS[(h*NCHUNK + chunk)*64 + (t >> 2) + 16*i] = s[i];
    }
}

// ---------------- K3c: reduce partial KV and partial S -----------------------
__global__ void k_rkv() {
    int h = blockIdx.x;
    int t = threadIdx.x;           // 256
    for (int idx = t; idx < 4096; idx += 256) {
        float acc = 0.f;
        #pragma unroll
        for (int c = 0; c < NCHUNK; c++)
            acc += g_pKV[(h*NCHUNK + c)*4096 + idx];
        g_KV[h*4096 + idx] = acc;
    }
    if (t < 64) {
        float acc = 0.f;
        #pragma unroll
        for (int c = 0; c < NCHUNK; c++)
            acc += g_pS[(h*NCHUNK + c)*64 + t];
        g_S[h*64 + t] = acc;
    }
}

// ---------------- K4: out[h*64+d][n] = (qf . KV) / (qf . S + eps) ------------
// 64(d) x 64(n) tile, K=64(e), 8x8 microtile, 64 threads, KV resident in smem.
__global__ void k_out(float* __restrict__ out) {
    __shared__ float sKV[64][68];  // [e][d]
    __shared__ float Bs[16][64];   // qf: [e][n]
    __shared__ float sS[64];
    int h  = blockIdx.x;           // 8
    int n0 = blockIdx.y * 64;      // 64 tiles
    int t  = threadIdx.x;          // 64
    int tx = t & 7, ty = t >> 3;

    #pragma unroll
    for (int i = 0; i < 16; i++) { // load whole KV 64x64
        int j = t + 64*i;
        int e = j >> 4, dc = (j & 15) * 4;
        *(float4*)&sKV[e][dc] = *(const float4*)&g_KV[h*4096 + e*64 + dc];
    }
    if (t < 64) sS[t] = g_S[h*64 + t];

    float acc[8][8] = {};
    float dacc[8] = {};

    for (int k0 = 0; k0 < 64; k0 += 16) {
        #pragma unroll
        for (int i = 0; i < 4; i++) {            // qf tile: 16(e) x 64(n)
            int j = t + 64*i;
            int bk = j >> 4, bn = (j & 15) * 4;
            *(float4*)&Bs[bk][bn] = *(const float4*)&g_qf[(h*64 + k0 + bk)*N_TOK + n0 + bn];
        }
        __syncthreads();
        #pragma unroll
        for (int kk = 0; kk < 16; kk++) {
            int e = k0 + kk;
            float a[8], b[8];
            *(float4*)&a[0] = *(const float4*)&sKV[e][ty*8];
            *(float4*)&a[4] = *(const float4*)&sKV[e][ty*8 + 4];
            *(float4*)&b[0] = *(const float4*)&Bs[kk][tx*8];
            *(float4*)&b[4] = *(const float4*)&Bs[kk][tx*8 + 4];
            float sv = sS[e];
            #pragma unroll
            for (int j = 0; j < 8; j++) dacc[j] += sv * b[j];
            #pragma unroll
            for (int i = 0; i < 8; i++)
                #pragma unroll
                for (int j = 0; j < 8; j++)
                    acc[i][j] += a[i] * b[j];
        }
        __syncthreads();
    }

    float inv[8];
    #pragma unroll
    for (int j = 0; j < 8; j++) inv[j] = 1.f / (dacc[j] + HEPS);

    int n = n0 + tx*8;
    #pragma unroll
    for (int i = 0; i < 8; i++) {
        int d = ty*8 + i;
        float4 c0 = {acc[i][0]*inv[0], acc[i][1]*inv[1], acc[i][2]*inv[2], acc[i][3]*inv[3]};
        float4 c1 = {acc[i][4]*inv[4], acc[i][5]*inv[5], acc[i][6]*inv[6], acc[i][7]*inv[7]};
        *(float4*)&out[(h*64 + d)*N_TOK + n]     = c0;
        *(float4*)&out[(h*64 + d)*N_TOK + n + 4] = c1;
    }
}

// -----------------------------------------------------------------------------
extern "C" void kernel_launch(void* const* d_in, const int* in_sizes, int n_in,
                              void* d_out, int out_size) {
    const float* x   = (const float*)d_in[0];   // [1,256,16,16,16]
    const float* Wq  = (const float*)d_in[1];   // [256,256]
    const float* Wk  = (const float*)d_in[2];   // [256,256]
    const float* Wv  = (const float*)d_in[3];   // [256,1,3,3,3]
    const float* bv  = (const float*)d_in[4];   // [256]
    const float* Wmq = (const float*)d_in[5];   // [64,64]
    const float* bmq = (const float*)d_in[6];   // [64]
    const float* Wmk = (const float*)d_in[7];   // [64,64]
    const float* bmk = (const float*)d_in[8];   // [64]
    const float* Wmv = (const float*)d_in[9];   // [64,64]
    const float* bmv = (const float*)d_in[10];  // [64]
    float* out = (float*)d_out;                 // [1,512,16,16,16]

    k_weff      <<<dim3(256, 2),        256>>>(Wq, Wk, Wmq, Wmk);
    k_gemm_hedge<<<dim3(4, 32, 2),      128>>>(x, bmq, bmk);
    k_conv      <<<dim3(256, 16), dim3(16,16)>>>(x, Wv, bv);
    k_vmix      <<<dim3(4, 64),          64>>>(Wmv, bmv);
    k_pkv       <<<dim3(8, NCHUNK),      64>>>();
    k_rkv       <<<8,                   256>>>();
    k_out       <<<dim3(8, 64),          64>>>(out);
}

// round 7
// speedup vs baseline: 1.3275x; 1.1655x over previous
#include <cuda_runtime.h>
#include <cuda_bf16.h>
#include <cstdint>

#define N_TOK 4096
#define HEPS 1e-6f
#define NCHUNK 32

// ---------------- scratch (device globals; no allocs allowed) ----------------
__device__ __align__(16) __nv_bfloat16 g_wq_hi[256*256];
__device__ __align__(16) __nv_bfloat16 g_wq_lo[256*256];
__device__ __align__(16) __nv_bfloat16 g_wk_hi[256*256];
__device__ __align__(16) __nv_bfloat16 g_wk_lo[256*256];
__device__ __align__(16) __nv_bfloat16 g_xt_hi[4096*256];   // x transposed [n][c]
__device__ __align__(16) __nv_bfloat16 g_xt_lo[4096*256];
__device__ __align__(16) float g_qf[8*64*N_TOK];   // [h][e][n], heads 4..7 = exp(-h)
__device__ __align__(16) float g_kf[8*64*N_TOK];
__device__ __align__(16) float g_vf[8*64*N_TOK];
__device__ __align__(16) float g_v [256*N_TOK];
__device__ __align__(16) float g_pKV[8*NCHUNK*64*64];
__device__ __align__(16) float g_pS [8*NCHUNK*64];
__device__ __align__(16) float g_KV[8*64*64];
__device__ __align__(16) float g_S [8*64];

// ==================== warp-MMA helpers =======================================
__device__ __forceinline__ uint32_t smem_u32(const void* p) {
    uint32_t a;
    asm("{ .reg .u64 tmp; cvta.to.shared.u64 tmp, %1; cvt.u32.u64 %0, tmp; }"
        : "=r"(a) : "l"(p));
    return a;
}
__device__ __forceinline__ void ldm_x4(uint32_t addr, uint32_t& r0, uint32_t& r1,
                                       uint32_t& r2, uint32_t& r3) {
    asm volatile("ldmatrix.sync.aligned.m8n8.x4.shared.b16 {%0,%1,%2,%3}, [%4];"
                 : "=r"(r0), "=r"(r1), "=r"(r2), "=r"(r3) : "r"(addr));
}
__device__ __forceinline__ void mma_bf16(float* c, const uint32_t* a,
                                         const uint32_t* b) {
    asm volatile(
        "mma.sync.aligned.m16n8k16.row.col.f32.bf16.bf16.f32 "
        "{%0,%1,%2,%3}, {%4,%5,%6,%7}, {%8,%9}, {%0,%1,%2,%3};"
        : "+f"(c[0]), "+f"(c[1]), "+f"(c[2]), "+f"(c[3])
        : "r"(a[0]), "r"(a[1]), "r"(a[2]), "r"(a[3]), "r"(b[0]), "r"(b[1]));
}

// ---------------- K0: Weff = Wm @ Wbig, split to bf16 hi/lo ------------------
__global__ void k_weff(const float* __restrict__ Wq, const float* __restrict__ Wk,
                       const float* __restrict__ Wmq, const float* __restrict__ Wmk) {
    int o = blockIdx.x;            // 0..255
    int c = threadIdx.x;           // 0..255
    int h = o >> 6, e = o & 63;
    const float* Wm = blockIdx.y ? Wmk : Wmq;
    const float* Wb = blockIdx.y ? Wk  : Wq;
    __shared__ float sWm[64];
    if (c < 64) sWm[c] = Wm[e*64 + c];
    __syncthreads();
    float acc = 0.f;
    #pragma unroll 8
    for (int d = 0; d < 64; d++)
        acc += sWm[d] * Wb[(h*64 + d)*256 + c];
    __nv_bfloat16 hi = __float2bfloat16(acc);
    __nv_bfloat16 lo = __float2bfloat16(acc - __bfloat162float(hi));
    if (blockIdx.y) { g_wk_hi[o*256 + c] = hi; g_wk_lo[o*256 + c] = lo; }
    else            { g_wq_hi[o*256 + c] = hi; g_wq_lo[o*256 + c] = lo; }
}

// ---------------- K0b: transpose + split x: xt[n][c] = x2[c][n] --------------
__global__ void k_xt(const float* __restrict__ x2) {
    __shared__ float s[32][33];
    int c0 = blockIdx.x * 32;      // 8 blocks
    int n0 = blockIdx.y * 32;      // 128 blocks
    int tx = threadIdx.x, ty = threadIdx.y;  // 32 x 8
    #pragma unroll
    for (int i = 0; i < 4; i++)
        s[ty + 8*i][tx] = x2[(c0 + ty + 8*i)*N_TOK + n0 + tx];
    __syncthreads();
    #pragma unroll
    for (int i = 0; i < 4; i++) {
        int n = n0 + ty + 8*i;
        float v = s[tx][ty + 8*i];
        __nv_bfloat16 hi = __float2bfloat16(v);
        __nv_bfloat16 lo = __float2bfloat16(v - __bfloat162float(hi));
        g_xt_hi[n*256 + c0 + tx] = hi;
        g_xt_lo[n*256 + c0 + tx] = lo;
    }
}

// ---------------- K1: hedgehog GEMM via mma.sync bf16 (split hi/lo) ----------
// D[128(M=o), 64(N=n)] = Weff[128,256] @ xT[64,256]^T.
// 8 warps (4M x 2N), each warp 32x32; K in 16-steps.
#define APITCH 24
__global__ void __launch_bounds__(256, 2)
k1mma(const float* __restrict__ bmq, const float* __restrict__ bmk) {
    __shared__ __nv_bfloat16 Ah[128][APITCH], Al[128][APITCH];
    __shared__ __nv_bfloat16 Bh[64][APITCH],  Bl[64][APITCH];

    int t = threadIdx.x;           // 256
    int lane = t & 31, wid = t >> 5;
    int wm = wid >> 1, wn = wid & 1;
    int m0 = blockIdx.x * 128;     // 2 M-tiles
    int n0 = blockIdx.y * 64;      // 64 N-tiles
    int z  = blockIdx.z;           // q / k
    const __nv_bfloat16* gAh = z ? g_wk_hi : g_wq_hi;
    const __nv_bfloat16* gAl = z ? g_wk_lo : g_wq_lo;
    const float* bm = z ? bmk : bmq;
    float* f        = z ? g_kf : g_qf;

    float acc[2][4][4] = {};       // [mtile][ntile][reg]

    // ldmatrix source addresses (fixed per thread)
    int a_row = (lane & 15), a_col = (lane >> 4) * 8;
    int b_row = (lane >> 4) * 8 + (lane & 7), b_col = ((lane >> 3) & 1) * 8;

    for (int k0 = 0; k0 < 256; k0 += 16) {
        // stage A: 128 rows x 16 halves, hi+lo (each thread: one 8-half chunk)
        int r  = t >> 1, cc = (t & 1) * 8;
        *(uint4*)&Ah[r][cc] = *(const uint4*)&gAh[(m0 + r)*256 + k0 + cc];
        *(uint4*)&Al[r][cc] = *(const uint4*)&gAl[(m0 + r)*256 + k0 + cc];
        // stage B: 64 rows x 16 halves, hi+lo (threads 0..127)
        if (t < 128) {
            int rb = t >> 1, cb = (t & 1) * 8;
            *(uint4*)&Bh[rb][cb] = *(const uint4*)&g_xt_hi[(n0 + rb)*256 + k0 + cb];
            *(uint4*)&Bl[rb][cb] = *(const uint4*)&g_xt_lo[(n0 + rb)*256 + k0 + cb];
        }
        __syncthreads();

        uint32_t ah[2][4], al[2][4], bh[4][2], bl[4][2];
        #pragma unroll
        for (int mt = 0; mt < 2; mt++) {
            uint32_t ad = smem_u32(&Ah[wm*32 + mt*16 + a_row][a_col]);
            ldm_x4(ad, ah[mt][0], ah[mt][1], ah[mt][2], ah[mt][3]);
            uint32_t ad2 = smem_u32(&Al[wm*32 + mt*16 + a_row][a_col]);
            ldm_x4(ad2, al[mt][0], al[mt][1], al[mt][2], al[mt][3]);
        }
        #pragma unroll
        for (int np = 0; np < 2; np++) {   // each x4 covers 2 n-tiles
            uint32_t bd = smem_u32(&Bh[wn*32 + np*16 + b_row][b_col]);
            ldm_x4(bd, bh[np*2][0], bh[np*2][1], bh[np*2+1][0], bh[np*2+1][1]);
            uint32_t bd2 = smem_u32(&Bl[wn*32 + np*16 + b_row][b_col]);
            ldm_x4(bd2, bl[np*2][0], bl[np*2][1], bl[np*2+1][0], bl[np*2+1][1]);
        }
        #pragma unroll
        for (int mt = 0; mt < 2; mt++)
            #pragma unroll
            for (int nt = 0; nt < 4; nt++) {
                mma_bf16(acc[mt][nt], ah[mt], bh[nt]);
                mma_bf16(acc[mt][nt], ah[mt], bl[nt]);
                mma_bf16(acc[mt][nt], al[mt], bh[nt]);
            }
        __syncthreads();
    }

    // epilogue: bias + exp(+/-), direct stores
    int qr = lane >> 2, qc = (lane & 3) * 2;
    #pragma unroll
    for (int mt = 0; mt < 2; mt++) {
        int ob = m0 + wm*32 + mt*16;
        int o0 = ob + qr, o1 = ob + qr + 8;
        float b0 = bm[o0 & 63], b1 = bm[o1 & 63];
        #pragma unroll
        for (int nt = 0; nt < 4; nt++) {
            int n = n0 + wn*32 + nt*8 + qc;
            float h00 = acc[mt][nt][0] + b0, h01 = acc[mt][nt][1] + b0;
            float h10 = acc[mt][nt][2] + b1, h11 = acc[mt][nt][3] + b1;
            float2 p0 = {__expf(h00),  __expf(h01)};
            float2 q0 = {__expf(-h00), __expf(-h01)};
            float2 p1 = {__expf(h10),  __expf(h11)};
            float2 q1 = {__expf(-h10), __expf(-h11)};
            *(float2*)&f[(size_t)o0*N_TOK + n]                = p0;
            *(float2*)&f[(size_t)o0*N_TOK + n + 4*64*N_TOK]   = q0;
            *(float2*)&f[(size_t)o1*N_TOK + n]                = p1;
            *(float2*)&f[(size_t)o1*N_TOK + n + 4*64*N_TOK]   = q1;
        }
    }
}

// ---------------- K2a: depthwise 3x3x3 conv over (H,W,D), pad 1 --------------
__global__ void k_conv(const float* __restrict__ x, const float* __restrict__ Wv,
                       const float* __restrict__ bv) {
    int c  = blockIdx.x;           // 256
    int hh = blockIdx.y;           // 16
    int dd = threadIdx.x;          // 16
    int ww = threadIdx.y;          // 16
    __shared__ float sw[27];
    int t = threadIdx.y*16 + threadIdx.x;
    if (t < 27) sw[t] = Wv[c*27 + t];
    __syncthreads();
    float acc = bv[c];
    #pragma unroll
    for (int a = -1; a <= 1; a++) {
        int hz = hh + a; if (hz < 0 || hz > 15) continue;
        #pragma unroll
        for (int b = -1; b <= 1; b++) {
            int wy = ww + b; if (wy < 0 || wy > 15) continue;
            #pragma unroll
            for (int cc = -1; cc <= 1; cc++) {
                int xd = dd + cc; if (xd < 0 || xd > 15) continue;
                acc += sw[(a+1)*9 + (b+1)*3 + (cc+1)] *
                       x[((c*16 + hz)*16 + wy)*16 + xd];
            }
        }
    }
    g_v[c*N_TOK + (hh*16 + ww)*16 + dd] = acc;
}

// ---------------- K2b: per-head v mix + exp: vf = exp(+-(Wmv@v + bmv)) -------
__global__ void k_vmix(const float* __restrict__ Wmv, const float* __restrict__ bmv) {
    __shared__ float As[16][68];   // Wmv^T staged: [d][e]
    __shared__ float Bs[16][64];   // v: [d][n]
    int h  = blockIdx.x;           // 4
    int n0 = blockIdx.y * 64;      // 64 tiles
    int t  = threadIdx.x;          // 64
    int tx = t & 7, ty = t >> 3;   // 8 x 8

    float acc[8][8] = {};

    for (int k0 = 0; k0 < 64; k0 += 16) {
        #pragma unroll
        for (int i = 0; i < 4; i++) {            // A: 64(e) x 16(d)
            int j = t + 64*i;
            int lm = j >> 2, lk = (j & 3) * 4;
            float4 av = *(const float4*)&Wmv[lm*64 + k0 + lk];
            As[lk+0][lm] = av.x; As[lk+1][lm] = av.y;
            As[lk+2][lm] = av.z; As[lk+3][lm] = av.w;
        }
        #pragma unroll
        for (int i = 0; i < 4; i++) {            // B: 16(d) x 64(n)
            int j = t + 64*i;
            int bk = j >> 4, bn = (j & 15) * 4;
            *(float4*)&Bs[bk][bn] = *(const float4*)&g_v[(h*64 + k0 + bk)*N_TOK + n0 + bn];
        }
        __syncthreads();
        #pragma unroll
        for (int kk = 0; kk < 16; kk++) {
            float a[8], b[8];
            *(float4*)&a[0] = *(const float4*)&As[kk][ty*8];
            *(float4*)&a[4] = *(const float4*)&As[kk][ty*8 + 4];
            *(float4*)&b[0] = *(const float4*)&Bs[kk][tx*8];
            *(float4*)&b[4] = *(const float4*)&Bs[kk][tx*8 + 4];
            #pragma unroll
            for (int i = 0; i < 8; i++)
                #pragma unroll
                for (int j = 0; j < 8; j++)
                    acc[i][j] += a[i] * b[j];
        }
        __syncthreads();
    }

    int n = n0 + tx*8;
    #pragma unroll
    for (int i = 0; i < 8; i++) {
        int e = ty*8 + i;
        float bias = bmv[e];
        float hv[8];
        #pragma unroll
        for (int j = 0; j < 8; j++) hv[j] = acc[i][j] + bias;
        float4 p0, p1, m0v, m1v;
        p0.x = __expf(hv[0]);  p0.y = __expf(hv[1]);  p0.z = __expf(hv[2]);  p0.w = __expf(hv[3]);
        p1.x = __expf(hv[4]);  p1.y = __expf(hv[5]);  p1.z = __expf(hv[6]);  p1.w = __expf(hv[7]);
        m0v.x = __expf(-hv[0]); m0v.y = __expf(-hv[1]); m0v.z = __expf(-hv[2]); m0v.w = __expf(-hv[3]);
        m1v.x = __expf(-hv[4]); m1v.y = __expf(-hv[5]); m1v.z = __expf(-hv[6]); m1v.w = __expf(-hv[7]);
        float* dst = &g_vf[(h*64 + e)*N_TOK + n];
        *(float4*)&dst[0]               = p0;
        *(float4*)&dst[4]               = p1;
        *(float4*)&dst[4*64*N_TOK]      = m0v;
        *(float4*)&dst[4 + 4*64*N_TOK]  = m1v;
    }
}

// ---------------- K3b: partial KV[h][e][d] + partial S over a 128-token chunk
__global__ void k_pkv() {
    __shared__ float skt[16][68];  // kf transposed: [nn][e]
    __shared__ float svt[16][68];  // vf transposed: [nn][d]
    int h = blockIdx.x, chunk = blockIdx.y;
    int t = threadIdx.x;           // 64
    int tx = t & 7, ty = t >> 3;
    int base_n = chunk * 128;

    float acc[8][8] = {};
    float s[4] = {};               // partial S for rows e = (t>>2) + 16*i

    for (int sub = 0; sub < 8; sub++) {
        int n0 = base_n + sub * 16;
        #pragma unroll
        for (int i = 0; i < 4; i++) {
            int j = t + 64*i;
            int e = j >> 2, nf = (j & 3) * 4;
            float4 kq = *(const float4*)&g_kf[(h*64 + e)*N_TOK + n0 + nf];
            skt[nf+0][e] = kq.x; skt[nf+1][e] = kq.y;
            skt[nf+2][e] = kq.z; skt[nf+3][e] = kq.w;
            s[i] += (kq.x + kq.y) + (kq.z + kq.w);
            float4 vq = *(const float4*)&g_vf[(h*64 + e)*N_TOK + n0 + nf];
            svt[nf+0][e] = vq.x; svt[nf+1][e] = vq.y;
            svt[nf+2][e] = vq.z; svt[nf+3][e] = vq.w;
        }
        __syncthreads();
        #pragma unroll
        for (int nn = 0; nn < 16; nn++) {
            float a[8], b[8];
            *(float4*)&a[0] = *(const float4*)&skt[nn][ty*8];
            *(float4*)&a[4] = *(const float4*)&skt[nn][ty*8 + 4];
            *(float4*)&b[0] = *(const float4*)&svt[nn][tx*8];
            *(float4*)&b[4] = *(const float4*)&svt[nn][tx*8 + 4];
            #pragma unroll
            for (int i = 0; i < 8; i++)
                #pragma unroll
                for (int j = 0; j < 8; j++)
                    acc[i][j] += a[i] * b[j];
        }
        __syncthreads();
    }

    float* dst = &g_pKV[(h*NCHUNK + chunk)*64*64];
    #pragma unroll
    for (int i = 0; i < 8; i++) {
        float4 c0 = {acc[i][0], acc[i][1], acc[i][2], acc[i][3]};
        float4 c1 = {acc[i][4], acc[i][5], acc[i][6], acc[i][7]};
        *(float4*)&dst[(ty*8 + i)*64 + tx*8]     = c0;
        *(float4*)&dst[(ty*8 + i)*64 + tx*8 + 4] = c1;
    }

    #pragma unroll
    for (int i = 0; i < 4; i++) {
        s[i] += __shfl_down_sync(0xffffffffu, s[i], 2);
        s[i] += __shfl_down_sync(0xffffffffu, s[i], 1);
    }
    if ((t & 3) == 0) {
        #pragma unroll
        for (int i = 0; i < 4; i++)
            g_pS[(h*NCHUNK + chunk)*64 + (t >> 2) + 16*i] = s[i];
    }
}

// ---------------- K3c: reduce partial KV and partial S -----------------------
__global__ void k_rkv() {
    int h = blockIdx.x;
    int t = threadIdx.x;           // 256
    for (int idx = t; idx < 4096; idx += 256) {
        float acc = 0.f;
        #pragma unroll
        for (int c = 0; c < NCHUNK; c++)
            acc += g_pKV[(h*NCHUNK + c)*4096 + idx];
        g_KV[h*4096 + idx] = acc;
    }
    if (t < 64) {
        float acc = 0.f;
        #pragma unroll
        for (int c = 0; c < NCHUNK; c++)
            acc += g_pS[(h*NCHUNK + c)*64 + t];
        g_S[h*64 + t] = acc;
    }
}

// ---------------- K4: out[h*64+d][n] = (qf . KV) / (qf . S + eps) ------------
__global__ void k_out(float* __restrict__ out) {
    __shared__ float sKV[64][68];  // [e][d]
    __shared__ float Bs[16][64];   // qf: [e][n]
    __shared__ float sS[64];
    int h  = blockIdx.x;           // 8
    int n0 = blockIdx.y * 64;      // 64 tiles
    int t  = threadIdx.x;          // 64
    int tx = t & 7, ty = t >> 3;

    #pragma unroll
    for (int i = 0; i < 16; i++) {
        int j = t + 64*i;
        int e = j >> 4, dc = (j & 15) * 4;
        *(float4*)&sKV[e][dc] = *(const float4*)&g_KV[h*4096 + e*64 + dc];
    }
    if (t < 64) sS[t] = g_S[h*64 + t];

    float acc[8][8] = {};
    float dacc[8] = {};

    for (int k0 = 0; k0 < 64; k0 += 16) {
        #pragma unroll
        for (int i = 0; i < 4; i++) {
            int j = t + 64*i;
            int bk = j >> 4, bn = (j & 15) * 4;
            *(float4*)&Bs[bk][bn] = *(const float4*)&g_qf[(h*64 + k0 + bk)*N_TOK + n0 + bn];
        }
        __syncthreads();
        #pragma unroll
        for (int kk = 0; kk < 16; kk++) {
            int e = k0 + kk;
            float a[8], b[8];
            *(float4*)&a[0] = *(const float4*)&sKV[e][ty*8];
            *(float4*)&a[4] = *(const float4*)&sKV[e][ty*8 + 4];
            *(float4*)&b[0] = *(const float4*)&Bs[kk][tx*8];
            *(float4*)&b[4] = *(const float4*)&Bs[kk][tx*8 + 4];
            float sv = sS[e];
            #pragma unroll
            for (int j = 0; j < 8; j++) dacc[j] += sv * b[j];
            #pragma unroll
            for (int i = 0; i < 8; i++)
                #pragma unroll
                for (int j = 0; j < 8; j++)
                    acc[i][j] += a[i] * b[j];
        }
        __syncthreads();
    }

    float inv[8];
    #pragma unroll
    for (int j = 0; j < 8; j++) inv[j] = 1.f / (dacc[j] + HEPS);

    int n = n0 + tx*8;
    #pragma unroll
    for (int i = 0; i < 8; i++) {
        int d = ty*8 + i;
        float4 c0 = {acc[i][0]*inv[0], acc[i][1]*inv[1], acc[i][2]*inv[2], acc[i][3]*inv[3]};
        float4 c1 = {acc[i][4]*inv[4], acc[i][5]*inv[5], acc[i][6]*inv[6], acc[i][7]*inv[7]};
        *(float4*)&out[(h*64 + d)*N_TOK + n]     = c0;
        *(float4*)&out[(h*64 + d)*N_TOK + n + 4] = c1;
    }
}

// -----------------------------------------------------------------------------
extern "C" void kernel_launch(void* const* d_in, const int* in_sizes, int n_in,
                              void* d_out, int out_size) {
    const float* x   = (const float*)d_in[0];   // [1,256,16,16,16]
    const float* Wq  = (const float*)d_in[1];   // [256,256]
    const float* Wk  = (const float*)d_in[2];   // [256,256]
    const float* Wv  = (const float*)d_in[3];   // [256,1,3,3,3]
    const float* bv  = (const float*)d_in[4];   // [256]
    const float* Wmq = (const float*)d_in[5];   // [64,64]
    const float* bmq = (const float*)d_in[6];   // [64]
    const float* Wmk = (const float*)d_in[7];   // [64,64]
    const float* bmk = (const float*)d_in[8];   // [64]
    const float* Wmv = (const float*)d_in[9];   // [64,64]
    const float* bmv = (const float*)d_in[10];  // [64]
    float* out = (float*)d_out;                 // [1,512,16,16,16]

    k_weff <<<dim3(256, 2),        256>>>(Wq, Wk, Wmq, Wmk);
    k_xt   <<<dim3(8, 128), dim3(32, 8)>>>(x);
    k1mma  <<<dim3(2, 64, 2),      256>>>(bmq, bmk);
    k_conv <<<dim3(256, 16), dim3(16,16)>>>(x, Wv, bv);
    k_vmix <<<dim3(4, 64),          64>>>(Wmv, bmv);
    k_pkv  <<<dim3(8, NCHUNK),      64>>>();
    k_rkv  <<<8,                   256>>>();
    k_out  <<<dim3(8, 64),          64>>>(out);
}

// round 9
// speedup vs baseline: 1.4267x; 1.0748x over previous
#include <cuda_runtime.h>
#include <cuda_bf16.h>
#include <cstdint>

#define N_TOK 4096
#define HEPS 1e-6f
#define NCHUNK 32

// ---------------- scratch (device globals; no allocs allowed) ----------------
__device__ __align__(16) __nv_bfloat16 g_wq_hi[256*256];
__device__ __align__(16) __nv_bfloat16 g_wq_lo[256*256];
__device__ __align__(16) __nv_bfloat16 g_wk_hi[256*256];
__device__ __align__(16) __nv_bfloat16 g_wk_lo[256*256];
__device__ __align__(16) __nv_bfloat16 g_xt_hi[4096*256];   // x transposed [n][c]
__device__ __align__(16) __nv_bfloat16 g_xt_lo[4096*256];
__device__ __align__(16) float g_qf[8*64*N_TOK];   // [h][e][n], heads 4..7 = exp(-h)
__device__ __align__(16) float g_kf[8*64*N_TOK];
__device__ __align__(16) float g_vf[8*64*N_TOK];
__device__ __align__(16) float g_v [256*N_TOK];
__device__ __align__(16) float g_pKV[8*NCHUNK*64*64];
__device__ __align__(16) float g_pS [8*NCHUNK*64];
__device__ __align__(16) float g_KV[8*64*64];
__device__ __align__(16) float g_S [8*64];

// ==================== warp-MMA helpers =======================================
__device__ __forceinline__ uint32_t smem_u32(const void* p) {
    uint32_t a;
    asm("{ .reg .u64 tmp; cvta.to.shared.u64 tmp, %1; cvt.u32.u64 %0, tmp; }"
        : "=r"(a) : "l"(p));
    return a;
}
__device__ __forceinline__ void ldm_x4(uint32_t addr, uint32_t& r0, uint32_t& r1,
                                       uint32_t& r2, uint32_t& r3) {
    asm volatile("ldmatrix.sync.aligned.m8n8.x4.shared.b16 {%0,%1,%2,%3}, [%4];"
                 : "=r"(r0), "=r"(r1), "=r"(r2), "=r"(r3) : "r"(addr));
}
__device__ __forceinline__ void mma_bf16(float* c, const uint32_t* a,
                                         const uint32_t* b) {
    asm volatile(
        "mma.sync.aligned.m16n8k16.row.col.f32.bf16.bf16.f32 "
        "{%0,%1,%2,%3}, {%4,%5,%6,%7}, {%8,%9}, {%0,%1,%2,%3};"
        : "+f"(c[0]), "+f"(c[1]), "+f"(c[2]), "+f"(c[3])
        : "r"(a[0]), "r"(a[1]), "r"(a[2]), "r"(a[3]), "r"(b[0]), "r"(b[1]));
}

// ---------------- K0: Weff = Wm @ Wbig, split to bf16 hi/lo ------------------
__global__ void k_weff(const float* __restrict__ Wq, const float* __restrict__ Wk,
                       const float* __restrict__ Wmq, const float* __restrict__ Wmk) {
    int o = blockIdx.x;            // 0..255
    int c = threadIdx.x;           // 0..255
    int h = o >> 6, e = o & 63;
    const float* Wm = blockIdx.y ? Wmk : Wmq;
    const float* Wb = blockIdx.y ? Wk  : Wq;
    __shared__ float sWm[64];
    if (c < 64) sWm[c] = Wm[e*64 + c];
    __syncthreads();
    float acc = 0.f;
    #pragma unroll 8
    for (int d = 0; d < 64; d++)
        acc += sWm[d] * Wb[(h*64 + d)*256 + c];
    __nv_bfloat16 hi = __float2bfloat16(acc);
    __nv_bfloat16 lo = __float2bfloat16(acc - __bfloat162float(hi));
    if (blockIdx.y) { g_wk_hi[o*256 + c] = hi; g_wk_lo[o*256 + c] = lo; }
    else            { g_wq_hi[o*256 + c] = hi; g_wq_lo[o*256 + c] = lo; }
}

// ---------------- K0b: transpose + split x: xt[n][c] = x2[c][n] --------------
__global__ void k_xt(const float* __restrict__ x2) {
    __shared__ float s[32][33];
    int c0 = blockIdx.x * 32;      // 8 blocks
    int n0 = blockIdx.y * 32;      // 128 blocks
    int tx = threadIdx.x, ty = threadIdx.y;  // 32 x 8
    #pragma unroll
    for (int i = 0; i < 4; i++)
        s[ty + 8*i][tx] = x2[(c0 + ty + 8*i)*N_TOK + n0 + tx];
    __syncthreads();
    #pragma unroll
    for (int i = 0; i < 4; i++) {
        int n = n0 + ty + 8*i;
        float v = s[tx][ty + 8*i];
        __nv_bfloat16 hi = __float2bfloat16(v);
        __nv_bfloat16 lo = __float2bfloat16(v - __bfloat162float(hi));
        g_xt_hi[n*256 + c0 + tx] = hi;
        g_xt_lo[n*256 + c0 + tx] = lo;
    }
}

// ---------------- K1: hedgehog GEMM via mma.sync bf16 (split hi/lo) ----------
#define APITCH 24
__global__ void __launch_bounds__(256, 2)
k1mma(const float* __restrict__ bmq, const float* __restrict__ bmk) {
    __shared__ __nv_bfloat16 Ah[128][APITCH], Al[128][APITCH];
    __shared__ __nv_bfloat16 Bh[64][APITCH],  Bl[64][APITCH];

    int t = threadIdx.x;           // 256
    int lane = t & 31, wid = t >> 5;
    int wm = wid >> 1, wn = wid & 1;
    int m0 = blockIdx.x * 128;     // 2 M-tiles
    int n0 = blockIdx.y * 64;      // 64 N-tiles
    int z  = blockIdx.z;           // q / k
    const __nv_bfloat16* gAh = z ? g_wk_hi : g_wq_hi;
    const __nv_bfloat16* gAl = z ? g_wk_lo : g_wq_lo;
    const float* bm = z ? bmk : bmq;
    float* f        = z ? g_kf : g_qf;

    float acc[2][4][4] = {};       // [mtile][ntile][reg]

    int a_row = (lane & 15), a_col = (lane >> 4) * 8;
    int b_row = (lane >> 4) * 8 + (lane & 7), b_col = ((lane >> 3) & 1) * 8;

    for (int k0 = 0; k0 < 256; k0 += 16) {
        int r  = t >> 1, cc = (t & 1) * 8;
        *(uint4*)&Ah[r][cc] = *(const uint4*)&gAh[(m0 + r)*256 + k0 + cc];
        *(uint4*)&Al[r][cc] = *(const uint4*)&gAl[(m0 + r)*256 + k0 + cc];
        if (t < 128) {
            int rb = t >> 1, cb = (t & 1) * 8;
            *(uint4*)&Bh[rb][cb] = *(const uint4*)&g_xt_hi[(n0 + rb)*256 + k0 + cb];
            *(uint4*)&Bl[rb][cb] = *(const uint4*)&g_xt_lo[(n0 + rb)*256 + k0 + cb];
        }
        __syncthreads();

        uint32_t ah[2][4], al[2][4], bh[4][2], bl[4][2];
        #pragma unroll
        for (int mt = 0; mt < 2; mt++) {
            uint32_t ad = smem_u32(&Ah[wm*32 + mt*16 + a_row][a_col]);
            ldm_x4(ad, ah[mt][0], ah[mt][1], ah[mt][2], ah[mt][3]);
            uint32_t ad2 = smem_u32(&Al[wm*32 + mt*16 + a_row][a_col]);
            ldm_x4(ad2, al[mt][0], al[mt][1], al[mt][2], al[mt][3]);
        }
        #pragma unroll
        for (int np = 0; np < 2; np++) {
            uint32_t bd = smem_u32(&Bh[wn*32 + np*16 + b_row][b_col]);
            ldm_x4(bd, bh[np*2][0], bh[np*2][1], bh[np*2+1][0], bh[np*2+1][1]);
            uint32_t bd2 = smem_u32(&Bl[wn*32 + np*16 + b_row][b_col]);
            ldm_x4(bd2, bl[np*2][0], bl[np*2][1], bl[np*2+1][0], bl[np*2+1][1]);
        }
        #pragma unroll
        for (int mt = 0; mt < 2; mt++)
            #pragma unroll
            for (int nt = 0; nt < 4; nt++) {
                mma_bf16(acc[mt][nt], ah[mt], bh[nt]);
                mma_bf16(acc[mt][nt], ah[mt], bl[nt]);
                mma_bf16(acc[mt][nt], al[mt], bh[nt]);
            }
        __syncthreads();
    }

    int qr = lane >> 2, qc = (lane & 3) * 2;
    #pragma unroll
    for (int mt = 0; mt < 2; mt++) {
        int ob = m0 + wm*32 + mt*16;
        int o0 = ob + qr, o1 = ob + qr + 8;
        float b0 = bm[o0 & 63], b1 = bm[o1 & 63];
        #pragma unroll
        for (int nt = 0; nt < 4; nt++) {
            int n = n0 + wn*32 + nt*8 + qc;
            float h00 = acc[mt][nt][0] + b0, h01 = acc[mt][nt][1] + b0;
            float h10 = acc[mt][nt][2] + b1, h11 = acc[mt][nt][3] + b1;
            float2 p0 = {__expf(h00),  __expf(h01)};
            float2 q0 = {__expf(-h00), __expf(-h01)};
            float2 p1 = {__expf(h10),  __expf(h11)};
            float2 q1 = {__expf(-h10), __expf(-h11)};
            *(float2*)&f[(size_t)o0*N_TOK + n]                = p0;
            *(float2*)&f[(size_t)o0*N_TOK + n + 4*64*N_TOK]   = q0;
            *(float2*)&f[(size_t)o1*N_TOK + n]                = p1;
            *(float2*)&f[(size_t)o1*N_TOK + n + 4*64*N_TOK]   = q1;
        }
    }
}

// ---------------- K2a: depthwise 3x3x3 conv, padded-smem, branch-free --------
// One block per channel. Padded volume 18 x 18 x 19 floats in smem.
#define CP_W 19
#define CP_R 342          // 18*19
__global__ void __launch_bounds__(256) k_conv(const float* __restrict__ x,
                                              const float* __restrict__ Wv,
                                              const float* __restrict__ bv) {
    __shared__ float sx[18*CP_R];  // 6156 floats
    __shared__ float sw[27];
    int c = blockIdx.x;            // 256
    int t = threadIdx.x;           // 256
    for (int i = t; i < 18*CP_R; i += 256) sx[i] = 0.f;
    if (t < 27) sw[t] = Wv[c*27 + t];
    __syncthreads();
    for (int i = t; i < 4096; i += 256) {
        int hh = i >> 8, ww = (i >> 4) & 15, dd = i & 15;
        sx[(hh+1)*CP_R + (ww+1)*CP_W + dd + 1] = x[c*4096 + i];
    }
    __syncthreads();

    int hh = t >> 4, ww = t & 15;
    float bias = bv[c];
    float acc[16];
    #pragma unroll
    for (int d = 0; d < 16; d++) acc[d] = bias;
    #pragma unroll
    for (int a = 0; a < 3; a++) {
        #pragma unroll
        for (int b = 0; b < 3; b++) {
            const float* row = &sx[(hh + a)*CP_R + (ww + b)*CP_W];
            float w0 = sw[a*9 + b*3 + 0];
            float w1 = sw[a*9 + b*3 + 1];
            float w2 = sw[a*9 + b*3 + 2];
            float r[18];
            #pragma unroll
            for (int d = 0; d < 18; d++) r[d] = row[d];
            #pragma unroll
            for (int d = 0; d < 16; d++)
                acc[d] += w0*r[d] + w1*r[d+1] + w2*r[d+2];
        }
    }
    float* dst = &g_v[c*N_TOK + (hh*16 + ww)*16];
    #pragma unroll
    for (int d = 0; d < 16; d += 4) {
        float4 o = {acc[d], acc[d+1], acc[d+2], acc[d+3]};
        *(float4*)&dst[d] = o;
    }
}

// ---------------- K2b: per-head v mix + exp (128 threads, 8x4 utile) ---------
__global__ void __launch_bounds__(128) k_vmix(const float* __restrict__ Wmv,
                                              const float* __restrict__ bmv) {
    __shared__ float As[16][68];   // Wmv^T staged: [d][e]
    __shared__ float Bs[16][64];   // v: [d][n]
    int h  = blockIdx.x;           // 4
    int n0 = blockIdx.y * 64;      // 64 tiles
    int t  = threadIdx.x;          // 128
    int tx = t & 15, ty = t >> 4;  // 16(n) x 8(e)

    float acc[8][4] = {};

    for (int k0 = 0; k0 < 64; k0 += 16) {
        #pragma unroll
        for (int i = 0; i < 2; i++) {            // A: 64(e) x 16(d)
            int j = t + 128*i;
            int lm = j >> 2, lk = (j & 3) * 4;
            float4 av = *(const float4*)&Wmv[lm*64 + k0 + lk];
            As[lk+0][lm] = av.x; As[lk+1][lm] = av.y;
            As[lk+2][lm] = av.z; As[lk+3][lm] = av.w;
        }
        #pragma unroll
        for (int i = 0; i < 2; i++) {            // B: 16(d) x 64(n)
            int j = t + 128*i;
            int bk = j >> 4, bn = (j & 15) * 4;
            *(float4*)&Bs[bk][bn] = *(const float4*)&g_v[(h*64 + k0 + bk)*N_TOK + n0 + bn];
        }
        __syncthreads();
        #pragma unroll
        for (int kk = 0; kk < 16; kk++) {
            float a[8], b[4];
            *(float4*)&a[0] = *(const float4*)&As[kk][ty*8];
            *(float4*)&a[4] = *(const float4*)&As[kk][ty*8 + 4];
            *(float4*)&b[0] = *(const float4*)&Bs[kk][tx*4];
            #pragma unroll
            for (int i = 0; i < 8; i++)
                #pragma unroll
                for (int j = 0; j < 4; j++)
                    acc[i][j] += a[i] * b[j];
        }
        __syncthreads();
    }

    int n = n0 + tx*4;
    #pragma unroll
    for (int i = 0; i < 8; i++) {
        int e = ty*8 + i;
        float bias = bmv[e];
        float h0 = acc[i][0] + bias, h1 = acc[i][1] + bias;
        float h2 = acc[i][2] + bias, h3 = acc[i][3] + bias;
        float4 p = {__expf(h0),  __expf(h1),  __expf(h2),  __expf(h3)};
        float4 m = {__expf(-h0), __expf(-h1), __expf(-h2), __expf(-h3)};
        float* dst = &g_vf[(h*64 + e)*N_TOK + n];
        *(float4*)&dst[0]          = p;
        *(float4*)&dst[4*64*N_TOK] = m;
    }
}

// ---------------- K3b: partial KV + partial S (128 threads, 8x4 utile) -------
__global__ void __launch_bounds__(128) k_pkv() {
    __shared__ float skt[16][68];  // kf transposed: [nn][e]
    __shared__ float svt[16][68];  // vf transposed: [nn][d]
    int h = blockIdx.x, chunk = blockIdx.y;
    int t = threadIdx.x;           // 128
    int tx = t & 15, ty = t >> 4;
    int base_n = chunk * 128;

    float acc[8][4] = {};
    float s[2] = {};               // partial S for e = (t>>2) and (t>>2)+32

    for (int sub = 0; sub < 8; sub++) {
        int n0 = base_n + sub * 16;
        #pragma unroll
        for (int i = 0; i < 2; i++) {
            int j = t + 128*i;
            int e = j >> 2, nf = (j & 3) * 4;
            float4 kq = *(const float4*)&g_kf[(h*64 + e)*N_TOK + n0 + nf];
            skt[nf+0][e] = kq.x; skt[nf+1][e] = kq.y;
            skt[nf+2][e] = kq.z; skt[nf+3][e] = kq.w;
            s[i] += (kq.x + kq.y) + (kq.z + kq.w);
            float4 vq = *(const float4*)&g_vf[(h*64 + e)*N_TOK + n0 + nf];
            svt[nf+0][e] = vq.x; svt[nf+1][e] = vq.y;
            svt[nf+2][e] = vq.z; svt[nf+3][e] = vq.w;
        }
        __syncthreads();
        #pragma unroll
        for (int nn = 0; nn < 16; nn++) {
            float a[8], b[4];
            *(float4*)&a[0] = *(const float4*)&skt[nn][ty*8];
            *(float4*)&a[4] = *(const float4*)&skt[nn][ty*8 + 4];
            *(float4*)&b[0] = *(const float4*)&svt[nn][tx*4];
            #pragma unroll
            for (int i = 0; i < 8; i++)
                #pragma unroll
                for (int j = 0; j < 4; j++)
                    acc[i][j] += a[i] * b[j];
        }
        __syncthreads();
    }

    float* dst = &g_pKV[(h*NCHUNK + chunk)*64*64];
    #pragma unroll
    for (int i = 0; i < 8; i++) {
        float4 c0 = {acc[i][0], acc[i][1], acc[i][2], acc[i][3]};
        *(float4*)&dst[(ty*8 + i)*64 + tx*4] = c0;
    }

    #pragma unroll
    for (int i = 0; i < 2; i++) {
        s[i] += __shfl_down_sync(0xffffffffu, s[i], 2);
        s[i] += __shfl_down_sync(0xffffffffu, s[i], 1);
    }
    if ((t & 3) == 0) {
        g_pS[(h*NCHUNK + chunk)*64 + (t >> 2)]      = s[0];
        g_pS[(h*NCHUNK + chunk)*64 + (t >> 2) + 32] = s[1];
    }
}

// ---------------- K3c: reduce partial KV and partial S -----------------------
__global__ void k_rkv() {
    int h = blockIdx.x;
    int t = threadIdx.x;           // 256
    for (int idx = t; idx < 4096; idx += 256) {
        float acc = 0.f;
        #pragma unroll
        for (int c = 0; c < NCHUNK; c++)
            acc += g_pKV[(h*NCHUNK + c)*4096 + idx];
        g_KV[h*4096 + idx] = acc;
    }
    if (t < 64) {
        float acc = 0.f;
        #pragma unroll
        for (int c = 0; c < NCHUNK; c++)
            acc += g_pS[(h*NCHUNK + c)*64 + t];
        g_S[h*64 + t] = acc;
    }
}

// ---------------- K4: out = (qf . KV) / (qf . S + eps) (128 thr, 8x4) --------
__global__ void __launch_bounds__(128) k_out(float* __restrict__ out) {
    __shared__ float sKV[64][68];  // [e][d]
    __shared__ float Bs[16][64];   // qf: [e][n]
    __shared__ float sS[64];
    int h  = blockIdx.x;           // 8
    int n0 = blockIdx.y * 64;      // 64 tiles
    int t  = threadIdx.x;          // 128
    int tx = t & 15, ty = t >> 4;

    #pragma unroll
    for (int i = 0; i < 8; i++) {
        int j = t + 128*i;
        int e = j >> 4, dc = (j & 15) * 4;
        *(float4*)&sKV[e][dc] = *(const float4*)&g_KV[h*4096 + e*64 + dc];
    }
    if (t < 64) sS[t] = g_S[h*64 + t];

    float acc[8][4] = {};
    float dacc[4] = {};

    for (int k0 = 0; k0 < 64; k0 += 16) {
        #pragma unroll
        for (int i = 0; i < 2; i++) {
            int j = t + 128*i;
            int bk = j >> 4, bn = (j & 15) * 4;
            *(float4*)&Bs[bk][bn] = *(const float4*)&g_qf[(h*64 + k0 + bk)*N_TOK + n0 + bn];
        }
        __syncthreads();
        #pragma unroll
        for (int kk = 0; kk < 16; kk++) {
            int e = k0 + kk;
            float a[8], b[4];
            *(float4*)&a[0] = *(const float4*)&sKV[e][ty*8];
            *(float4*)&a[4] = *(const float4*)&sKV[e][ty*8 + 4];
            *(float4*)&b[0] = *(const float4*)&Bs[kk][tx*4];
            float sv = sS[e];
            #pragma unroll
            for (int j = 0; j < 4; j++) dacc[j] += sv * b[j];
            #pragma unroll
            for (int i = 0; i < 8; i++)
                #pragma unroll
                for (int j = 0; j < 4; j++)
                    acc[i][j] += a[i] * b[j];
        }
        __syncthreads();
    }

    float inv[4];
    #pragma unroll
    for (int j = 0; j < 4; j++) inv[j] = 1.f / (dacc[j] + HEPS);

    int n = n0 + tx*4;
    #pragma unroll
    for (int i = 0; i < 8; i++) {
        int d = ty*8 + i;
        float4 c0 = {acc[i][0]*inv[0], acc[i][1]*inv[1], acc[i][2]*inv[2], acc[i][3]*inv[3]};
        *(float4*)&out[(h*64 + d)*N_TOK + n] = c0;
    }
}

// -----------------------------------------------------------------------------
extern "C" void kernel_launch(void* const* d_in, const int* in_sizes, int n_in,
                              void* d_out, int out_size) {
    const float* x   = (const float*)d_in[0];   // [1,256,16,16,16]
    const float* Wq  = (const float*)d_in[1];   // [256,256]
    const float* Wk  = (const float*)d_in[2];   // [256,256]
    const float* Wv  = (const float*)d_in[3];   // [256,1,3,3,3]
    const float* bv  = (const float*)d_in[4];   // [256]
    const float* Wmq = (const float*)d_in[5];   // [64,64]
    const float* bmq = (const float*)d_in[6];   // [64]
    const float* Wmk = (const float*)d_in[7];   // [64,64]
    const float* bmk = (const float*)d_in[8];   // [64]
    const float* Wmv = (const float*)d_in[9];   // [64,64]
    const float* bmv = (const float*)d_in[10];  // [64]
    float* out = (float*)d_out;                 // [1,512,16,16,16]

    k_weff <<<dim3(256, 2),        256>>>(Wq, Wk, Wmq, Wmk);
    k_xt   <<<dim3(8, 128), dim3(32, 8)>>>(x);
    k1mma  <<<dim3(2, 64, 2),      256>>>(bmq, bmk);
    k_conv <<<256,                 256>>>(x, Wv, bv);
    k_vmix <<<dim3(4, 64),         128>>>(Wmv, bmv);
    k_pkv  <<<dim3(8, NCHUNK),     128>>>();
    k_rkv  <<<8,                   256>>>();
    k_out  <<<dim3(8, 64),         128>>>(out);
}

// round 10
// speedup vs baseline: 1.5040x; 1.0541x over previous
#include <cuda_runtime.h>
#include <cuda_bf16.h>
#include <cstdint>

#define N_TOK 4096
#define HEPS 1e-6f
#define NCHUNK 32

// ---------------- scratch (device globals; no allocs allowed) ----------------
__device__ __align__(16) __nv_bfloat16 g_wq_hi[256*256];
__device__ __align__(16) __nv_bfloat16 g_wq_lo[256*256];
__device__ __align__(16) __nv_bfloat16 g_wk_hi[256*256];
__device__ __align__(16) __nv_bfloat16 g_wk_lo[256*256];
__device__ __align__(16) __nv_bfloat16 g_xt_hi[4096*256];   // x transposed [n][c]
__device__ __align__(16) __nv_bfloat16 g_xt_lo[4096*256];
__device__ __align__(16) float g_qf[8*64*N_TOK];   // [h][e][n], heads 4..7 = exp(-h)
__device__ __align__(16) float g_kf[8*64*N_TOK];
__device__ __align__(16) float g_vf[8*64*N_TOK];
__device__ __align__(16) float g_v [256*N_TOK];
__device__ __align__(16) float g_pKV[8*NCHUNK*64*64];
__device__ __align__(16) float g_pS [8*NCHUNK*64];
__device__ __align__(16) float g_KV[8*64*64];
__device__ __align__(16) float g_S [8*64];

// ==================== warp-MMA / async helpers ===============================
__device__ __forceinline__ uint32_t smem_u32(const void* p) {
    uint32_t a;
    asm("{ .reg .u64 tmp; cvta.to.shared.u64 tmp, %1; cvt.u32.u64 %0, tmp; }"
        : "=r"(a) : "l"(p));
    return a;
}
__device__ __forceinline__ void ldm_x4(uint32_t addr, uint32_t& r0, uint32_t& r1,
                                       uint32_t& r2, uint32_t& r3) {
    asm volatile("ldmatrix.sync.aligned.m8n8.x4.shared.b16 {%0,%1,%2,%3}, [%4];"
                 : "=r"(r0), "=r"(r1), "=r"(r2), "=r"(r3) : "r"(addr));
}
__device__ __forceinline__ void mma_bf16(float* c, const uint32_t* a,
                                         const uint32_t* b) {
    asm volatile(
        "mma.sync.aligned.m16n8k16.row.col.f32.bf16.bf16.f32 "
        "{%0,%1,%2,%3}, {%4,%5,%6,%7}, {%8,%9}, {%0,%1,%2,%3};"
        : "+f"(c[0]), "+f"(c[1]), "+f"(c[2]), "+f"(c[3])
        : "r"(a[0]), "r"(a[1]), "r"(a[2]), "r"(a[3]), "r"(b[0]), "r"(b[1]));
}
__device__ __forceinline__ void cp16(uint32_t s, const void* g) {
    asm volatile("cp.async.cg.shared.global [%0], [%1], 16;" :: "r"(s), "l"(g));
}
#define CP_COMMIT() asm volatile("cp.async.commit_group;" ::: "memory")
#define CP_WAIT1()  asm volatile("cp.async.wait_group 1;"  ::: "memory")
#define CP_WAIT0()  asm volatile("cp.async.wait_group 0;"  ::: "memory")

// ---------------- K0: Weff = Wm @ Wbig, split to bf16 hi/lo ------------------
__global__ void k_weff(const float* __restrict__ Wq, const float* __restrict__ Wk,
                       const float* __restrict__ Wmq, const float* __restrict__ Wmk) {
    int o = blockIdx.x;            // 0..255
    int c = threadIdx.x;           // 0..255
    int h = o >> 6, e = o & 63;
    const float* Wm = blockIdx.y ? Wmk : Wmq;
    const float* Wb = blockIdx.y ? Wk  : Wq;
    __shared__ float sWm[64];
    if (c < 64) sWm[c] = Wm[e*64 + c];
    __syncthreads();
    float acc = 0.f;
    #pragma unroll 8
    for (int d = 0; d < 64; d++)
        acc += sWm[d] * Wb[(h*64 + d)*256 + c];
    __nv_bfloat16 hi = __float2bfloat16(acc);
    __nv_bfloat16 lo = __float2bfloat16(acc - __bfloat162float(hi));
    if (blockIdx.y) { g_wk_hi[o*256 + c] = hi; g_wk_lo[o*256 + c] = lo; }
    else            { g_wq_hi[o*256 + c] = hi; g_wq_lo[o*256 + c] = lo; }
}

// ---------------- K0b: transpose + split x: xt[n][c] = x2[c][n] --------------
__global__ void k_xt(const float* __restrict__ x2) {
    __shared__ float s[32][33];
    int c0 = blockIdx.x * 32;      // 8 blocks
    int n0 = blockIdx.y * 32;      // 128 blocks
    int tx = threadIdx.x, ty = threadIdx.y;  // 32 x 8
    #pragma unroll
    for (int i = 0; i < 4; i++)
        s[ty + 8*i][tx] = x2[(c0 + ty + 8*i)*N_TOK + n0 + tx];
    __syncthreads();
    #pragma unroll
    for (int i = 0; i < 4; i++) {
        int n = n0 + ty + 8*i;
        float v = s[tx][ty + 8*i];
        __nv_bfloat16 hi = __float2bfloat16(v);
        __nv_bfloat16 lo = __float2bfloat16(v - __bfloat162float(hi));
        g_xt_hi[n*256 + c0 + tx] = hi;
        g_xt_lo[n*256 + c0 + tx] = lo;
    }
}

// ---------------- K1: hedgehog GEMM via mma.sync bf16, cp.async 2-stage ------
#define APITCH 24
__global__ void __launch_bounds__(256, 2)
k1mma(const float* __restrict__ bmq, const float* __restrict__ bmk) {
    __shared__ __nv_bfloat16 Ah[2][128][APITCH], Al[2][128][APITCH];
    __shared__ __nv_bfloat16 Bh[2][64][APITCH],  Bl[2][64][APITCH];

    int t = threadIdx.x;           // 256
    int lane = t & 31, wid = t >> 5;
    int wm = wid >> 1, wn = wid & 1;
    int m0 = blockIdx.x * 128;     // 2 M-tiles
    int n0 = blockIdx.y * 64;      // 64 N-tiles
    int z  = blockIdx.z;           // q / k
    const __nv_bfloat16* gAh = z ? g_wk_hi : g_wq_hi;
    const __nv_bfloat16* gAl = z ? g_wk_lo : g_wq_lo;
    const float* bm = z ? bmk : bmq;
    float* f        = z ? g_kf : g_qf;

    float acc[2][4][4] = {};       // [mtile][ntile][reg]

    int a_row = (lane & 15), a_col = (lane >> 4) * 8;
    int b_row = (lane >> 4) * 8 + (lane & 7), b_col = ((lane >> 3) & 1) * 8;

    // per-thread staging coords
    int r  = t >> 1, cc = (t & 1) * 8;          // A: 128 rows x 16 cols
    const __nv_bfloat16* pAh = &gAh[(m0 + r)*256 + cc];
    const __nv_bfloat16* pAl = &gAl[(m0 + r)*256 + cc];
    const __nv_bfloat16* pBh = &g_xt_hi[(n0 + r)*256 + cc];  // valid when t<128
    const __nv_bfloat16* pBl = &g_xt_lo[(n0 + r)*256 + cc];

    // prefetch stage 0
    {
        cp16(smem_u32(&Ah[0][r][cc]), pAh);
        cp16(smem_u32(&Al[0][r][cc]), pAl);
        if (t < 128) {
            cp16(smem_u32(&Bh[0][r][cc]), pBh);
            cp16(smem_u32(&Bl[0][r][cc]), pBl);
        }
        CP_COMMIT();
    }

    for (int ks = 0; ks < 16; ks++) {
        if (ks < 15) {
            int s = (ks + 1) & 1, k0 = (ks + 1) * 16;
            cp16(smem_u32(&Ah[s][r][cc]), pAh + k0);
            cp16(smem_u32(&Al[s][r][cc]), pAl + k0);
            if (t < 128) {
                cp16(smem_u32(&Bh[s][r][cc]), pBh + k0);
                cp16(smem_u32(&Bl[s][r][cc]), pBl + k0);
            }
            CP_COMMIT();
            CP_WAIT1();
        } else {
            CP_WAIT0();
        }
        __syncthreads();
        int s = ks & 1;

        uint32_t ah[2][4], al[2][4], bh[4][2], bl[4][2];
        #pragma unroll
        for (int mt = 0; mt < 2; mt++) {
            uint32_t ad = smem_u32(&Ah[s][wm*32 + mt*16 + a_row][a_col]);
            ldm_x4(ad, ah[mt][0], ah[mt][1], ah[mt][2], ah[mt][3]);
            uint32_t ad2 = smem_u32(&Al[s][wm*32 + mt*16 + a_row][a_col]);
            ldm_x4(ad2, al[mt][0], al[mt][1], al[mt][2], al[mt][3]);
        }
        #pragma unroll
        for (int np = 0; np < 2; np++) {
            uint32_t bd = smem_u32(&Bh[s][wn*32 + np*16 + b_row][b_col]);
            ldm_x4(bd, bh[np*2][0], bh[np*2][1], bh[np*2+1][0], bh[np*2+1][1]);
            uint32_t bd2 = smem_u32(&Bl[s][wn*32 + np*16 + b_row][b_col]);
            ldm_x4(bd2, bl[np*2][0], bl[np*2][1], bl[np*2+1][0], bl[np*2+1][1]);
        }
        #pragma unroll
        for (int mt = 0; mt < 2; mt++)
            #pragma unroll
            for (int nt = 0; nt < 4; nt++) {
                mma_bf16(acc[mt][nt], ah[mt], bh[nt]);
                mma_bf16(acc[mt][nt], ah[mt], bl[nt]);
                mma_bf16(acc[mt][nt], al[mt], bh[nt]);
            }
        __syncthreads();
    }

    int qr = lane >> 2, qc = (lane & 3) * 2;
    #pragma unroll
    for (int mt = 0; mt < 2; mt++) {
        int ob = m0 + wm*32 + mt*16;
        int o0 = ob + qr, o1 = ob + qr + 8;
        float b0 = bm[o0 & 63], b1 = bm[o1 & 63];
        #pragma unroll
        for (int nt = 0; nt < 4; nt++) {
            int n = n0 + wn*32 + nt*8 + qc;
            float h00 = acc[mt][nt][0] + b0, h01 = acc[mt][nt][1] + b0;
            float h10 = acc[mt][nt][2] + b1, h11 = acc[mt][nt][3] + b1;
            float2 p0 = {__expf(h00),  __expf(h01)};
            float2 q0 = {__expf(-h00), __expf(-h01)};
            float2 p1 = {__expf(h10),  __expf(h11)};
            float2 q1 = {__expf(-h10), __expf(-h11)};
            *(float2*)&f[(size_t)o0*N_TOK + n]                = p0;
            *(float2*)&f[(size_t)o0*N_TOK + n + 4*64*N_TOK]   = q0;
            *(float2*)&f[(size_t)o1*N_TOK + n]                = p1;
            *(float2*)&f[(size_t)o1*N_TOK + n + 4*64*N_TOK]   = q1;
        }
    }
}

// ---------------- K2a: depthwise 3x3x3 conv, (channel x h-slab) blocks -------
// grid (256, 4); each block: channel c, h rows [4*hs, 4*hs+3].
// Padded smem volume: 6 h-planes x 18(w) x 19(d pitch).
#define CV_PD 19
#define CV_PP 342          // 18*19 plane pitch
__global__ void __launch_bounds__(256) k_conv(const float* __restrict__ x,
                                              const float* __restrict__ Wv,
                                              const float* __restrict__ bv) {
    __shared__ float sx[6*CV_PP]; // 2052 floats
    __shared__ float sw[27];
    int c  = blockIdx.x;           // 256
    int hs = blockIdx.y;           // 4
    int t  = threadIdx.x;          // 256
    int ww = t >> 4, dd = t & 15;

    for (int i = t; i < 6*CV_PP; i += 256) sx[i] = 0.f;
    if (t < 27) sw[t] = Wv[c*27 + t];
    __syncthreads();
    #pragma unroll
    for (int p = 0; p < 6; p++) {
        int hz = hs*4 - 1 + p;
        if (hz >= 0 && hz < 16)
            sx[p*CV_PP + (ww+1)*CV_PD + dd + 1] = x[c*4096 + hz*256 + ww*16 + dd];
    }
    __syncthreads();

    float bias = bv[c];
    float acc[4] = {bias, bias, bias, bias};
    #pragma unroll
    for (int a = 0; a < 3; a++) {
        #pragma unroll
        for (int b = 0; b < 3; b++) {
            float w0 = sw[a*9 + b*3 + 0];
            float w1 = sw[a*9 + b*3 + 1];
            float w2 = sw[a*9 + b*3 + 2];
            #pragma unroll
            for (int hh = 0; hh < 4; hh++) {
                const float* row = &sx[(hh + a)*CV_PP + (ww + b)*CV_PD + dd];
                acc[hh] += w0*row[0] + w1*row[1] + w2*row[2];
            }
        }
    }
    #pragma unroll
    for (int hh = 0; hh < 4; hh++)
        g_v[c*N_TOK + (hs*4 + hh)*256 + ww*16 + dd] = acc[hh];
}

// ---------------- K2b: per-head v mix + exp (128 threads, 8x4 utile) ---------
__global__ void __launch_bounds__(128) k_vmix(const float* __restrict__ Wmv,
                                              const float* __restrict__ bmv) {
    __shared__ float As[16][68];   // Wmv^T staged: [d][e]
    __shared__ float Bs[16][64];   // v: [d][n]
    int h  = blockIdx.x;           // 4
    int n0 = blockIdx.y * 64;      // 64 tiles
    int t  = threadIdx.x;          // 128
    int tx = t & 15, ty = t >> 4;  // 16(n) x 8(e)

    float acc[8][4] = {};

    for (int k0 = 0; k0 < 64; k0 += 16) {
        #pragma unroll
        for (int i = 0; i < 2; i++) {            // A: 64(e) x 16(d)
            int j = t + 128*i;
            int lm = j >> 2, lk = (j & 3) * 4;
            float4 av = *(const float4*)&Wmv[lm*64 + k0 + lk];
            As[lk+0][lm] = av.x; As[lk+1][lm] = av.y;
            As[lk+2][lm] = av.z; As[lk+3][lm] = av.w;
        }
        #pragma unroll
        for (int i = 0; i < 2; i++) {            // B: 16(d) x 64(n)
            int j = t + 128*i;
            int bk = j >> 4, bn = (j & 15) * 4;
            *(float4*)&Bs[bk][bn] = *(const float4*)&g_v[(h*64 + k0 + bk)*N_TOK + n0 + bn];
        }
        __syncthreads();
        #pragma unroll
        for (int kk = 0; kk < 16; kk++) {
            float a[8], b[4];
            *(float4*)&a[0] = *(const float4*)&As[kk][ty*8];
            *(float4*)&a[4] = *(const float4*)&As[kk][ty*8 + 4];
            *(float4*)&b[0] = *(const float4*)&Bs[kk][tx*4];
            #pragma unroll
            for (int i = 0; i < 8; i++)
                #pragma unroll
                for (int j = 0; j < 4; j++)
                    acc[i][j] += a[i] * b[j];
        }
        __syncthreads();
    }

    int n = n0 + tx*4;
    #pragma unroll
    for (int i = 0; i < 8; i++) {
        int e = ty*8 + i;
        float bias = bmv[e];
        float h0 = acc[i][0] + bias, h1 = acc[i][1] + bias;
        float h2 = acc[i][2] + bias, h3 = acc[i][3] + bias;
        float4 p = {__expf(h0),  __expf(h1),  __expf(h2),  __expf(h3)};
        float4 m = {__expf(-h0), __expf(-h1), __expf(-h2), __expf(-h3)};
        float* dst = &g_vf[(h*64 + e)*N_TOK + n];
        *(float4*)&dst[0]          = p;
        *(float4*)&dst[4*64*N_TOK] = m;
    }
}

// ---------------- K3b: partial KV + partial S (128 threads, 8x4 utile) -------
__global__ void __launch_bounds__(128) k_pkv() {
    __shared__ float skt[16][68];  // kf transposed: [nn][e]
    __shared__ float svt[16][68];  // vf transposed: [nn][d]
    int h = blockIdx.x, chunk = blockIdx.y;
    int t = threadIdx.x;           // 128
    int tx = t & 15, ty = t >> 4;
    int base_n = chunk * 128;

    float acc[8][4] = {};
    float s[2] = {};               // partial S for e = (t>>2) and (t>>2)+32

    for (int sub = 0; sub < 8; sub++) {
        int n0 = base_n + sub * 16;
        #pragma unroll
        for (int i = 0; i < 2; i++) {
            int j = t + 128*i;
            int e = j >> 2, nf = (j & 3) * 4;
            float4 kq = *(const float4*)&g_kf[(h*64 + e)*N_TOK + n0 + nf];
            skt[nf+0][e] = kq.x; skt[nf+1][e] = kq.y;
            skt[nf+2][e] = kq.z; skt[nf+3][e] = kq.w;
            s[i] += (kq.x + kq.y) + (kq.z + kq.w);
            float4 vq = *(const float4*)&g_vf[(h*64 + e)*N_TOK + n0 + nf];
            svt[nf+0][e] = vq.x; svt[nf+1][e] = vq.y;
            svt[nf+2][e] = vq.z; svt[nf+3][e] = vq.w;
        }
        __syncthreads();
        #pragma unroll
        for (int nn = 0; nn < 16; nn++) {
            float a[8], b[4];
            *(float4*)&a[0] = *(const float4*)&skt[nn][ty*8];
            *(float4*)&a[4] = *(const float4*)&skt[nn][ty*8 + 4];
            *(float4*)&b[0] = *(const float4*)&svt[nn][tx*4];
            #pragma unroll
            for (int i = 0; i < 8; i++)
                #pragma unroll
                for (int j = 0; j < 4; j++)
                    acc[i][j] += a[i] * b[j];
        }
        __syncthreads();
    }

    float* dst = &g_pKV[(h*NCHUNK + chunk)*64*64];
    #pragma unroll
    for (int i = 0; i < 8; i++) {
        float4 c0 = {acc[i][0], acc[i][1], acc[i][2], acc[i][3]};
        *(float4*)&dst[(ty*8 + i)*64 + tx*4] = c0;
    }

    #pragma unroll
    for (int i = 0; i < 2; i++) {
        s[i] += __shfl_down_sync(0xffffffffu, s[i], 2);
        s[i] += __shfl_down_sync(0xffffffffu, s[i], 1);
    }
    if ((t & 3) == 0) {
        g_pS[(h*NCHUNK + chunk)*64 + (t >> 2)]      = s[0];
        g_pS[(h*NCHUNK + chunk)*64 + (t >> 2) + 32] = s[1];
    }
}

// ---------------- K3c: reduce partial KV and partial S -----------------------
__global__ void k_rkv() {
    int h = blockIdx.x;
    int t = threadIdx.x;           // 256
    for (int idx = t; idx < 4096; idx += 256) {
        float acc = 0.f;
        #pragma unroll
        for (int c = 0; c < NCHUNK; c++)
            acc += g_pKV[(h*NCHUNK + c)*4096 + idx];
        g_KV[h*4096 + idx] = acc;
    }
    if (t < 64) {
        float acc = 0.f;
        #pragma unroll
        for (int c = 0; c < NCHUNK; c++)
            acc += g_pS[(h*NCHUNK + c)*64 + t];
        g_S[h*64 + t] = acc;
    }
}

// ---------------- K4: out = (qf . KV) / (qf . S + eps) (128 thr, 8x4) --------
__global__ void __launch_bounds__(128) k_out(float* __restrict__ out) {
    __shared__ float sKV[64][68];  // [e][d]
    __shared__ float Bs[16][64];   // qf: [e][n]
    __shared__ float sS[64];
    int h  = blockIdx.x;           // 8
    int n0 = blockIdx.y * 64;      // 64 tiles
    int t  = threadIdx.x;          // 128
    int tx = t & 15, ty = t >> 4;

    #pragma unroll
    for (int i = 0; i < 8; i++) {
        int j = t + 128*i;
        int e = j >> 4, dc = (j & 15) * 4;
        *(float4*)&sKV[e][dc] = *(const float4*)&g_KV[h*4096 + e*64 + dc];
    }
    if (t < 64) sS[t] = g_S[h*64 + t];

    float acc[8][4] = {};
    float dacc[4] = {};

    for (int k0 = 0; k0 < 64; k0 += 16) {
        #pragma unroll
        for (int i = 0; i < 2; i++) {
            int j = t + 128*i;
            int bk = j >> 4, bn = (j & 15) * 4;
            *(float4*)&Bs[bk][bn] = *(const float4*)&g_qf[(h*64 + k0 + bk)*N_TOK + n0 + bn];
        }
        __syncthreads();
        #pragma unroll
        for (int kk = 0; kk < 16; kk++) {
            int e = k0 + kk;
            float a[8], b[4];
            *(float4*)&a[0] = *(const float4*)&sKV[e][ty*8];
            *(float4*)&a[4] = *(const float4*)&sKV[e][ty*8 + 4];
            *(float4*)&b[0] = *(const float4*)&Bs[kk][tx*4];
            float sv = sS[e];
            #pragma unroll
            for (int j = 0; j < 4; j++) dacc[j] += sv * b[j];
            #pragma unroll
            for (int i = 0; i < 8; i++)
                #pragma unroll
                for (int j = 0; j < 4; j++)
                    acc[i][j] += a[i] * b[j];
        }
        __syncthreads();
    }

    float inv[4];
    #pragma unroll
    for (int j = 0; j < 4; j++) inv[j] = 1.f / (dacc[j] + HEPS);

    int n = n0 + tx*4;
    #pragma unroll
    for (int i = 0; i < 8; i++) {
        int d = ty*8 + i;
        float4 c0 = {acc[i][0]*inv[0], acc[i][1]*inv[1], acc[i][2]*inv[2], acc[i][3]*inv[3]};
        *(float4*)&out[(h*64 + d)*N_TOK + n] = c0;
    }
}

// -----------------------------------------------------------------------------
extern "C" void kernel_launch(void* const* d_in, const int* in_sizes, int n_in,
                              void* d_out, int out_size) {
    const float* x   = (const float*)d_in[0];   // [1,256,16,16,16]
    const float* Wq  = (const float*)d_in[1];   // [256,256]
    const float* Wk  = (const float*)d_in[2];   // [256,256]
    const float* Wv  = (const float*)d_in[3];   // [256,1,3,3,3]
    const float* bv  = (const float*)d_in[4];   // [256]
    const float* Wmq = (const float*)d_in[5];   // [64,64]
    const float* bmq = (const float*)d_in[6];   // [64]
    const float* Wmk = (const float*)d_in[7];   // [64,64]
    const float* bmk = (const float*)d_in[8];   // [64]
    const float* Wmv = (const float*)d_in[9];   // [64,64]
    const float* bmv = (const float*)d_in[10];  // [64]
    float* out = (float*)d_out;                 // [1,512,16,16,16]

    k_weff <<<dim3(256, 2),        256>>>(Wq, Wk, Wmq, Wmk);
    k_xt   <<<dim3(8, 128), dim3(32, 8)>>>(x);
    k1mma  <<<dim3(2, 64, 2),      256>>>(bmq, bmk);
    k_conv <<<dim3(256, 4),        256>>>(x, Wv, bv);
    k_vmix <<<dim3(4, 64),         128>>>(Wmv, bmv);
    k_pkv  <<<dim3(8, NCHUNK),     128>>>();
    k_rkv  <<<8,                   256>>>();
    k_out  <<<dim3(8, 64),         128>>>(out);
}

// round 14
// speedup vs baseline: 1.5433x; 1.0261x over previous
#include <cuda_runtime.h>
#include <cuda_bf16.h>
#include <cstdint>

#define N_TOK 4096
#define HEPS 1e-6f
#define NCHUNK 32

// ---------------- scratch (device globals; no allocs allowed) ----------------
__device__ __align__(16) __nv_bfloat16 g_wq_hi[256*256];
__device__ __align__(16) __nv_bfloat16 g_wq_lo[256*256];
__device__ __align__(16) __nv_bfloat16 g_wk_hi[256*256];
__device__ __align__(16) __nv_bfloat16 g_wk_lo[256*256];
__device__ __align__(16) __nv_bfloat16 g_xt_hi[4096*256];   // x transposed [n][c]
__device__ __align__(16) __nv_bfloat16 g_xt_lo[4096*256];
// positive heads only; heads 4..7 are reciprocals computed on the fly
__device__ __align__(16) float g_qf[4*64*N_TOK];   // [h][e][n] = exp(+h)
__device__ __align__(16) float g_kf[4*64*N_TOK];
__device__ __align__(16) float g_vf[4*64*N_TOK];
__device__ __align__(16) float g_v [256*N_TOK];
__device__ __align__(16) float g_pKV[8*NCHUNK*64*64];
__device__ __align__(16) float g_pS [8*NCHUNK*64];
__device__ __align__(16) float g_KV[8*64*64];
__device__ __align__(16) float g_S [8*64];

// ==================== helpers ================================================
__device__ __forceinline__ uint32_t smem_u32(const void* p) {
    uint32_t a;
    asm("{ .reg .u64 tmp; cvta.to.shared.u64 tmp, %1; cvt.u32.u64 %0, tmp; }"
        : "=r"(a) : "l"(p));
    return a;
}
__device__ __forceinline__ void ldm_x4(uint32_t addr, uint32_t& r0, uint32_t& r1,
                                       uint32_t& r2, uint32_t& r3) {
    asm volatile("ldmatrix.sync.aligned.m8n8.x4.shared.b16 {%0,%1,%2,%3}, [%4];"
                 : "=r"(r0), "=r"(r1), "=r"(r2), "=r"(r3) : "r"(addr));
}
__device__ __forceinline__ void mma_bf16(float* c, const uint32_t* a,
                                         const uint32_t* b) {
    asm volatile(
        "mma.sync.aligned.m16n8k16.row.col.f32.bf16.bf16.f32 "
        "{%0,%1,%2,%3}, {%4,%5,%6,%7}, {%8,%9}, {%0,%1,%2,%3};"
        : "+f"(c[0]), "+f"(c[1]), "+f"(c[2]), "+f"(c[3])
        : "r"(a[0]), "r"(a[1]), "r"(a[2]), "r"(a[3]), "r"(b[0]), "r"(b[1]));
}
__device__ __forceinline__ void cp16(uint32_t s, const void* g) {
    asm volatile("cp.async.cg.shared.global [%0], [%1], 16;" :: "r"(s), "l"(g));
}
#define CP_COMMIT() asm volatile("cp.async.commit_group;" ::: "memory")
#define CP_WAIT1()  asm volatile("cp.async.wait_group 1;"  ::: "memory")
#define CP_WAIT0()  asm volatile("cp.async.wait_group 0;"  ::: "memory")
__device__ __forceinline__ float rcpf(float x) {
    float r;
    asm("rcp.approx.f32 %0, %1;" : "=f"(r) : "f"(x));
    return r;
}
__device__ __forceinline__ float4 rcp4(float4 v) {
    return make_float4(rcpf(v.x), rcpf(v.y), rcpf(v.z), rcpf(v.w));
}

// ---------------- K0: fused prep — Weff split (blocks 0..511) + x transpose --
__global__ void __launch_bounds__(256) k_prep(
        const float* __restrict__ Wq, const float* __restrict__ Wk,
        const float* __restrict__ Wmq, const float* __restrict__ Wmk,
        const float* __restrict__ x2) {
    __shared__ float sWm[64];
    __shared__ float sx[32][33];
    int b = blockIdx.x;
    int t = threadIdx.x;
    if (b < 512) {
        int o = b & 255, y = b >> 8;
        int h = o >> 6, e = o & 63;
        const float* Wm = y ? Wmk : Wmq;
        const float* Wb = y ? Wk  : Wq;
        if (t < 64) sWm[t] = Wm[e*64 + t];
        __syncthreads();
        float acc = 0.f;
        #pragma unroll 8
        for (int d = 0; d < 64; d++)
            acc += sWm[d] * Wb[(h*64 + d)*256 + t];
        __nv_bfloat16 hi = __float2bfloat16(acc);
        __nv_bfloat16 lo = __float2bfloat16(acc - __bfloat162float(hi));
        if (y) { g_wk_hi[o*256 + t] = hi; g_wk_lo[o*256 + t] = lo; }
        else   { g_wq_hi[o*256 + t] = hi; g_wq_lo[o*256 + t] = lo; }
    } else {
        int bb = b - 512;              // 0..1023
        int c0 = (bb >> 7) * 32;       // 8 slabs
        int n0 = (bb & 127) * 32;      // 128 slabs
        int tx = t & 31, ty = t >> 5;  // 32 x 8
        #pragma unroll
        for (int i = 0; i < 4; i++)
            sx[ty + 8*i][tx] = x2[(c0 + ty + 8*i)*N_TOK + n0 + tx];
        __syncthreads();
        #pragma unroll
        for (int i = 0; i < 4; i++) {
            int n = n0 + ty + 8*i;
            float v = sx[tx][ty + 8*i];
            __nv_bfloat16 hi = __float2bfloat16(v);
            __nv_bfloat16 lo = __float2bfloat16(v - __bfloat162float(hi));
            g_xt_hi[n*256 + c0 + tx] = hi;
            g_xt_lo[n*256 + c0 + tx] = lo;
        }
    }
}

// ---------------- K1: hedgehog GEMM via mma.sync bf16, cp.async 2-stage ------
#define APITCH 24
__global__ void __launch_bounds__(256, 2)
k1mma(const float* __restrict__ bmq, const float* __restrict__ bmk) {
    __shared__ __nv_bfloat16 Ah[2][128][APITCH], Al[2][128][APITCH];
    __shared__ __nv_bfloat16 Bh[2][64][APITCH],  Bl[2][64][APITCH];

    int t = threadIdx.x;           // 256
    int lane = t & 31, wid = t >> 5;
    int wm = wid >> 1, wn = wid & 1;
    int m0 = blockIdx.x * 128;     // 2 M-tiles
    int n0 = blockIdx.y * 64;      // 64 N-tiles
    int z  = blockIdx.z;           // q / k
    const __nv_bfloat16* gAh = z ? g_wk_hi : g_wq_hi;
    const __nv_bfloat16* gAl = z ? g_wk_lo : g_wq_lo;
    const float* bm = z ? bmk : bmq;
    float* f        = z ? g_kf : g_qf;

    float acc[2][4][4] = {};       // [mtile][ntile][reg]

    int a_row = (lane & 15), a_col = (lane >> 4) * 8;
    int b_row = (lane >> 4) * 8 + (lane & 7), b_col = ((lane >> 3) & 1) * 8;

    int r  = t >> 1, cc = (t & 1) * 8;          // A: 128 rows x 16 cols
    int rb = (t < 128) ? r : 0;                 // clamp: B pointers stay in-bounds
    const __nv_bfloat16* pAh = &gAh[(m0 + r)*256 + cc];
    const __nv_bfloat16* pAl = &gAl[(m0 + r)*256 + cc];
    const __nv_bfloat16* pBh = &g_xt_hi[(n0 + rb)*256 + cc];
    const __nv_bfloat16* pBl = &g_xt_lo[(n0 + rb)*256 + cc];

    {   // prefetch stage 0
        cp16(smem_u32(&Ah[0][r][cc]), pAh);
        cp16(smem_u32(&Al[0][r][cc]), pAl);
        if (t < 128) {
            cp16(smem_u32(&Bh[0][rb][cc]), pBh);
            cp16(smem_u32(&Bl[0][rb][cc]), pBl);
        }
        CP_COMMIT();
    }

    for (int ks = 0; ks < 16; ks++) {
        if (ks < 15) {
            int s = (ks + 1) & 1, k0 = (ks + 1) * 16;
            cp16(smem_u32(&Ah[s][r][cc]), pAh + k0);
            cp16(smem_u32(&Al[s][r][cc]), pAl + k0);
            if (t < 128) {
                cp16(smem_u32(&Bh[s][rb][cc]), pBh + k0);
                cp16(smem_u32(&Bl[s][rb][cc]), pBl + k0);
            }
            CP_COMMIT();
            CP_WAIT1();
        } else {
            CP_WAIT0();
        }
        __syncthreads();
        int s = ks & 1;

        uint32_t ah[2][4], al[2][4], bh[4][2], bl[4][2];
        #pragma unroll
        for (int mt = 0; mt < 2; mt++) {
            uint32_t ad = smem_u32(&Ah[s][wm*32 + mt*16 + a_row][a_col]);
            ldm_x4(ad, ah[mt][0], ah[mt][1], ah[mt][2], ah[mt][3]);
            uint32_t ad2 = smem_u32(&Al[s][wm*32 + mt*16 + a_row][a_col]);
            ldm_x4(ad2, al[mt][0], al[mt][1], al[mt][2], al[mt][3]);
        }
        #pragma unroll
        for (int np = 0; np < 2; np++) {
            uint32_t bd = smem_u32(&Bh[s][wn*32 + np*16 + b_row][b_col]);
            ldm_x4(bd, bh[np*2][0], bh[np*2][1], bh[np*2+1][0], bh[np*2+1][1]);
            uint32_t bd2 = smem_u32(&Bl[s][wn*32 + np*16 + b_row][b_col]);
            ldm_x4(bd2, bl[np*2][0], bl[np*2][1], bl[np*2+1][0], bl[np*2+1][1]);
        }
        #pragma unroll
        for (int mt = 0; mt < 2; mt++)
            #pragma unroll
            for (int nt = 0; nt < 4; nt++) {
                mma_bf16(acc[mt][nt], ah[mt], bh[nt]);
                mma_bf16(acc[mt][nt], ah[mt], bl[nt]);
                mma_bf16(acc[mt][nt], al[mt], bh[nt]);
            }
        __syncthreads();
    }

    // epilogue: bias + exp(+h) only (negative heads are reciprocals, on the fly)
    int qr = lane >> 2, qc = (lane & 3) * 2;
    #pragma unroll
    for (int mt = 0; mt < 2; mt++) {
        int ob = m0 + wm*32 + mt*16;
        int o0 = ob + qr, o1 = ob + qr + 8;
        float b0 = bm[o0 & 63], b1 = bm[o1 & 63];
        #pragma unroll
        for (int nt = 0; nt < 4; nt++) {
            int n = n0 + wn*32 + nt*8 + qc;
            float h00 = acc[mt][nt][0] + b0, h01 = acc[mt][nt][1] + b0;
            float h10 = acc[mt][nt][2] + b1, h11 = acc[mt][nt][3] + b1;
            float2 p0 = {__expf(h00), __expf(h01)};
            float2 p1 = {__expf(h10), __expf(h11)};
            *(float2*)&f[(size_t)o0*N_TOK + n] = p0;
            *(float2*)&f[(size_t)o1*N_TOK + n] = p1;
        }
    }
}

// ---------------- K2a: depthwise 3x3x3 conv, plane-major, LDS-minimized ------
#define CV_PD 19
#define CV_PP 342          // 18*19 plane pitch
__global__ void __launch_bounds__(256) k_conv(const float* __restrict__ x,
                                              const float* __restrict__ Wv,
                                              const float* __restrict__ bv) {
    __shared__ float sx[6*CV_PP]; // 2052 floats
    __shared__ float sw[27];
    int c  = blockIdx.x;           // 256
    int hs = blockIdx.y;           // 4
    int t  = threadIdx.x;          // 256
    int ww = t >> 4, dd = t & 15;

    for (int i = t; i < 6*CV_PP; i += 256) sx[i] = 0.f;
    if (t < 27) sw[t] = Wv[c*27 + t];
    __syncthreads();
    #pragma unroll
    for (int p = 0; p < 6; p++) {
        int hz = hs*4 - 1 + p;
        if (hz >= 0 && hz < 16)
            sx[p*CV_PP + (ww+1)*CV_PD + dd + 1] = x[c*4096 + hz*256 + ww*16 + dd];
    }
    __syncthreads();

    float bias = bv[c];
    float acc[4] = {bias, bias, bias, bias};
    #pragma unroll
    for (int p = 0; p < 6; p++) {
        #pragma unroll
        for (int b = 0; b < 3; b++) {
            const float* row = &sx[p*CV_PP + (ww + b)*CV_PD + dd];
            float r0 = row[0], r1 = row[1], r2 = row[2];
            #pragma unroll
            for (int a = 0; a < 3; a++) {
                int hh = p - a;            // plane p feeds output row hh with tap a
                if (hh >= 0 && hh < 4)     // compile-time resolved
                    acc[hh] += sw[a*9 + b*3 + 0]*r0 + sw[a*9 + b*3 + 1]*r1
                             + sw[a*9 + b*3 + 2]*r2;
            }
        }
    }
    #pragma unroll
    for (int hh = 0; hh < 4; hh++)
        g_v[c*N_TOK + (hs*4 + hh)*256 + ww*16 + dd] = acc[hh];
}

// ---------------- K2b: per-head v mix + exp(+) (128 threads, 8x4 utile) ------
__global__ void __launch_bounds__(128) k_vmix(const float* __restrict__ Wmv,
                                              const float* __restrict__ bmv) {
    __shared__ float As[16][68];   // Wmv^T staged: [d][e]
    __shared__ float Bs[16][64];   // v: [d][n]
    int h  = blockIdx.x;           // 4
    int n0 = blockIdx.y * 64;      // 64 tiles
    int t  = threadIdx.x;          // 128
    int tx = t & 15, ty = t >> 4;  // 16(n) x 8(e)

    float acc[8][4] = {};

    for (int k0 = 0; k0 < 64; k0 += 16) {
        #pragma unroll
        for (int i = 0; i < 2; i++) {
            int j = t + 128*i;
            int lm = j >> 2, lk = (j & 3) * 4;
            float4 av = *(const float4*)&Wmv[lm*64 + k0 + lk];
            As[lk+0][lm] = av.x; As[lk+1][lm] = av.y;
            As[lk+2][lm] = av.z; As[lk+3][lm] = av.w;
        }
        #pragma unroll
        for (int i = 0; i < 2; i++) {
            int j = t + 128*i;
            int bk = j >> 4, bn = (j & 15) * 4;
            *(float4*)&Bs[bk][bn] = *(const float4*)&g_v[(h*64 + k0 + bk)*N_TOK + n0 + bn];
        }
        __syncthreads();
        #pragma unroll
        for (int kk = 0; kk < 16; kk++) {
            float a[8], b[4];
            *(float4*)&a[0] = *(const float4*)&As[kk][ty*8];
            *(float4*)&a[4] = *(const float4*)&As[kk][ty*8 + 4];
            *(float4*)&b[0] = *(const float4*)&Bs[kk][tx*4];
            #pragma unroll
            for (int i = 0; i < 8; i++)
                #pragma unroll
                for (int j = 0; j < 4; j++)
                    acc[i][j] += a[i] * b[j];
        }
        __syncthreads();
    }

    int n = n0 + tx*4;
    #pragma unroll
    for (int i = 0; i < 8; i++) {
        int e = ty*8 + i;
        float bias = bmv[e];
        float h0 = acc[i][0] + bias, h1 = acc[i][1] + bias;
        float h2 = acc[i][2] + bias, h3 = acc[i][3] + bias;
        float4 p = {__expf(h0), __expf(h1), __expf(h2), __expf(h3)};
        *(float4*)&g_vf[(h*64 + e)*N_TOK + n] = p;
    }
}

// ---------------- K3b: partial KV + partial S (rcp for neg heads) ------------
__global__ void __launch_bounds__(128) k_pkv() {
    __shared__ float skt[16][68];  // kf transposed: [nn][e]
    __shared__ float svt[16][68];  // vf transposed: [nn][d]
    int h = blockIdx.x, chunk = blockIdx.y;
    int hb = h & 3;
    bool neg = h >= 4;
    int t = threadIdx.x;           // 128
    int tx = t & 15, ty = t >> 4;
    int base_n = chunk * 128;

    float acc[8][4] = {};
    float s[2] = {};

    for (int sub = 0; sub < 8; sub++) {
        int n0 = base_n + sub * 16;
        #pragma unroll
        for (int i = 0; i < 2; i++) {
            int j = t + 128*i;
            int e = j >> 2, nf = (j & 3) * 4;
            float4 kq = *(const float4*)&g_kf[(hb*64 + e)*N_TOK + n0 + nf];
            if (neg) kq = rcp4(kq);
            skt[nf+0][e] = kq.x; skt[nf+1][e] = kq.y;
            skt[nf+2][e] = kq.z; skt[nf+3][e] = kq.w;
            s[i] += (kq.x + kq.y) + (kq.z + kq.w);
            float4 vq = *(const float4*)&g_vf[(hb*64 + e)*N_TOK + n0 + nf];
            if (neg) vq = rcp4(vq);
            svt[nf+0][e] = vq.x; svt[nf+1][e] = vq.y;
            svt[nf+2][e] = vq.z; svt[nf+3][e] = vq.w;
        }
        __syncthreads();
        #pragma unroll
        for (int nn = 0; nn < 16; nn++) {
            float a[8], b[4];
            *(float4*)&a[0] = *(const float4*)&skt[nn][ty*8];
            *(float4*)&a[4] = *(const float4*)&skt[nn][ty*8 + 4];
            *(float4*)&b[0] = *(const float4*)&svt[nn][tx*4];
            #pragma unroll
            for (int i = 0; i < 8; i++)
                #pragma unroll
                for (int j = 0; j < 4; j++)
                    acc[i][j] += a[i] * b[j];
        }
        __syncthreads();
    }

    float* dst = &g_pKV[(h*NCHUNK + chunk)*64*64];
    #pragma unroll
    for (int i = 0; i < 8; i++) {
        float4 c0 = {acc[i][0], acc[i][1], acc[i][2], acc[i][3]};
        *(float4*)&dst[(ty*8 + i)*64 + tx*4] = c0;
    }

    #pragma unroll
    for (int i = 0; i < 2; i++) {
        s[i] += __shfl_down_sync(0xffffffffu, s[i], 2);
        s[i] += __shfl_down_sync(0xffffffffu, s[i], 1);
    }
    if ((t & 3) == 0) {
        g_pS[(h*NCHUNK + chunk)*64 + (t >> 2)]      = s[0];
        g_pS[(h*NCHUNK + chunk)*64 + (t >> 2) + 32] = s[1];
    }
}

// ---------------- K3c: reduce partial KV and partial S -----------------------
__global__ void k_rkv() {
    int h = blockIdx.x;
    int t = threadIdx.x;           // 256
    for (int idx = t; idx < 4096; idx += 256) {
        float acc = 0.f;
        #pragma unroll
        for (int c = 0; c < NCHUNK; c++)
            acc += g_pKV[(h*NCHUNK + c)*4096 + idx];
        g_KV[h*4096 + idx] = acc;
    }
    if (t < 64) {
        float acc = 0.f;
        #pragma unroll
        for (int c = 0; c < NCHUNK; c++)
            acc += g_pS[(h*NCHUNK + c)*64 + t];
        g_S[h*64 + t] = acc;
    }
}

// ---------------- K4: out = (qf . KV) / (qf . S + eps) (rcp for neg heads) ---
__global__ void __launch_bounds__(128) k_out(float* __restrict__ out) {
    __shared__ float sKV[64][68];  // [e][d]
    __shared__ float Bs[16][64];   // qf: [e][n]
    __shared__ float sS[64];
    int h  = blockIdx.x;           // 8
    int hb = h & 3;
    bool neg = h >= 4;
    int n0 = blockIdx.y * 64;      // 64 tiles
    int t  = threadIdx.x;          // 128
    int tx = t & 15, ty = t >> 4;

    #pragma unroll
    for (int i = 0; i < 8; i++) {
        int j = t + 128*i;
        int e = j >> 4, dc = (j & 15) * 4;
        *(float4*)&sKV[e][dc] = *(const float4*)&g_KV[h*4096 + e*64 + dc];
    }
    if (t < 64) sS[t] = g_S[h*64 + t];

    float acc[8][4] = {};
    float dacc[4] = {};

    for (int k0 = 0; k0 < 64; k0 += 16) {
        #pragma unroll
        for (int i = 0; i < 2; i++) {
            int j = t + 128*i;
            int bk = j >> 4, bn = (j & 15) * 4;
            float4 qv = *(const float4*)&g_qf[(hb*64 + k0 + bk)*N_TOK + n0 + bn];
            if (neg) qv = rcp4(qv);
            *(float4*)&Bs[bk][bn] = qv;
        }
        __syncthreads();
        #pragma unroll
        for (int kk = 0; kk < 16; kk++) {
            int e = k0 + kk;
            float a[8], b[4];
            *(float4*)&a[0] = *(const float4*)&sKV[e][ty*8];
            *(float4*)&a[4] = *(const float4*)&sKV[e][ty*8 + 4];
            *(float4*)&b[0] = *(const float4*)&Bs[kk][tx*4];
            float sv = sS[e];
            #pragma unroll
            for (int j = 0; j < 4; j++) dacc[j] += sv * b[j];
            #pragma unroll
            for (int i = 0; i < 8; i++)
                #pragma unroll
                for (int j = 0; j < 4; j++)
                    acc[i][j] += a[i] * b[j];
        }
        __syncthreads();
    }

    float inv[4];
    #pragma unroll
    for (int j = 0; j < 4; j++) inv[j] = 1.f / (dacc[j] + HEPS);

    int n = n0 + tx*4;
    #pragma unroll
    for (int i = 0; i < 8; i++) {
        int d = ty*8 + i;
        float4 c0 = {acc[i][0]*inv[0], acc[i][1]*inv[1], acc[i][2]*inv[2], acc[i][3]*inv[3]};
        *(float4*)&out[(h*64 + d)*N_TOK + n] = c0;
    }
}

// -----------------------------------------------------------------------------
extern "C" void kernel_launch(void* const* d_in, const int* in_sizes, int n_in,
                              void* d_out, int out_size) {
    const float* x   = (const float*)d_in[0];   // [1,256,16,16,16]
    const float* Wq  = (const float*)d_in[1];   // [256,256]
    const float* Wk  = (const float*)d_in[2];   // [256,256]
    const float* Wv  = (const float*)d_in[3];   // [256,1,3,3,3]
    const float* bv  = (const float*)d_in[4];   // [256]
    const float* Wmq = (const float*)d_in[5];   // [64,64]
    const float* bmq = (const float*)d_in[6];   // [64]
    const float* Wmk = (const float*)d_in[7];   // [64,64]
    const float* bmk = (const float*)d_in[8];   // [64]
    const float* Wmv = (const float*)d_in[9];   // [64,64]
    const float* bmv = (const float*)d_in[10];  // [64]
    float* out = (float*)d_out;                 // [1,512,16,16,16]

    k_prep <<<1536,                256>>>(Wq, Wk, Wmq, Wmk, x);
    k1mma  <<<dim3(2, 64, 2),      256>>>(bmq, bmk);
    k_conv <<<dim3(256, 4),        256>>>(x, Wv, bv);
    k_vmix <<<dim3(4, 64),         128>>>(Wmv, bmv);
    k_pkv  <<<dim3(8, NCHUNK),     128>>>();
    k_rkv  <<<8,                   256>>>();
    k_out  <<<dim3(8, 64),         128>>>(out);
}